// round 1
// baseline (speedup 1.0000x reference)
#include <cuda_runtime.h>

#define BATCH 4
#define NPTS  4096
#define CIN   64
#define COUT  128
#define KNN   16

// Scratch (allocation-free rule: __device__ globals)
__device__ int   g_idx[BATCH * NPTS * KNN];
__device__ float g_featc[BATCH * NPTS * COUT];
__device__ float g_featn[BATCH * NPTS * COUT];

// ---------------------------------------------------------------------------
// Kernel 1: brute-force KNN (top-16 by neg squared distance, includes self)
// ---------------------------------------------------------------------------
__global__ void knn_kernel(const float* __restrict__ pos) {
    const int b = blockIdx.y;
    const int i = blockIdx.x * blockDim.x + threadIdx.x;   // query point
    const float* posb = pos + (size_t)b * NPTS * 3;

    const float qx = posb[i * 3 + 0];
    const float qy = posb[i * 3 + 1];
    const float qz = posb[i * 3 + 2];
    const float sqq = qx * qx + qy * qy + qz * qz;

    float bd[KNN];
    int   bi[KNN];
#pragma unroll
    for (int k = 0; k < KNN; k++) { bd[k] = -1e30f; bi[k] = 0; }

    __shared__ float spx[128], spy[128], spz[128], ssq[128];

    for (int j0 = 0; j0 < NPTS; j0 += 128) {
        __syncthreads();
        const int j = j0 + threadIdx.x;
        const float x = posb[j * 3 + 0];
        const float y = posb[j * 3 + 1];
        const float z = posb[j * 3 + 2];
        spx[threadIdx.x] = x;
        spy[threadIdx.x] = y;
        spz[threadIdx.x] = z;
        ssq[threadIdx.x] = x * x + y * y + z * z;
        __syncthreads();

#pragma unroll 4
        for (int jj = 0; jj < 128; jj++) {
            const float inner = qx * spx[jj] + qy * spy[jj] + qz * spz[jj];
            const float d = 2.0f * inner - sqq - ssq[jj];
            if (d > bd[KNN - 1]) {
                bd[KNN - 1] = d;
                bi[KNN - 1] = j0 + jj;
#pragma unroll
                for (int s = KNN - 1; s > 0; --s) {
                    if (bd[s] > bd[s - 1]) {
                        const float td = bd[s]; bd[s] = bd[s - 1]; bd[s - 1] = td;
                        const int   ti = bi[s]; bi[s] = bi[s - 1]; bi[s - 1] = ti;
                    }
                }
            }
        }
    }

    int* out = g_idx + ((size_t)b * NPTS + i) * KNN;
#pragma unroll
    for (int k = 0; k < KNN; k++) out[k] = bi[k];
}

// ---------------------------------------------------------------------------
// Kernel 2: feat_c = x @ Wc + bc ; feat_n = x @ Wn + bn   (dense, pre-gather)
// ---------------------------------------------------------------------------
__global__ void linear_kernel(const float* __restrict__ x,
                              const float* __restrict__ Wc, const float* __restrict__ bc,
                              const float* __restrict__ Wn, const float* __restrict__ bn) {
    const int row = blockIdx.x;        // 0..B*N-1
    const int col = threadIdx.x;       // 0..127

    __shared__ float xs[CIN];
    if (col < CIN) xs[col] = x[(size_t)row * CIN + col];
    __syncthreads();

    float ac = bc[col];
    float an = bn[col];
#pragma unroll 8
    for (int c = 0; c < CIN; c++) {
        const float xv = xs[c];
        ac = fmaf(xv, Wc[c * COUT + col], ac);
        an = fmaf(xv, Wn[c * COUT + col], an);
    }
    g_featc[(size_t)row * COUT + col] = ac;
    g_featn[(size_t)row * COUT + col] = an;
}

// ---------------------------------------------------------------------------
// Fused attention kernel helpers
// ---------------------------------------------------------------------------
// acc[4] += (sh[0:128]) dot 4 columns of W (cols c4..c4+3), W is [128,128] row-major
__device__ __forceinline__ float4 dot128(float4 acc, const float* __restrict__ W,
                                         const float* sh, int c4) {
#pragma unroll 4
    for (int c0 = 0; c0 < COUT; c0 += 4) {
        const float4 s = *(const float4*)(sh + c0);
        const float* wp = W + c0 * COUT + c4;
        const float4 w0 = *(const float4*)(wp);
        const float4 w1 = *(const float4*)(wp + COUT);
        const float4 w2 = *(const float4*)(wp + 2 * COUT);
        const float4 w3 = *(const float4*)(wp + 3 * COUT);
        acc.x = fmaf(s.x, w0.x, fmaf(s.y, w1.x, fmaf(s.z, w2.x, fmaf(s.w, w3.x, acc.x))));
        acc.y = fmaf(s.x, w0.y, fmaf(s.y, w1.y, fmaf(s.z, w2.y, fmaf(s.w, w3.y, acc.y))));
        acc.z = fmaf(s.x, w0.z, fmaf(s.y, w1.z, fmaf(s.z, w2.z, fmaf(s.w, w3.z, acc.z))));
        acc.w = fmaf(s.x, w0.w, fmaf(s.y, w1.w, fmaf(s.z, w2.w, fmaf(s.w, w3.w, acc.w))));
    }
    return acc;
}

// ---------------------------------------------------------------------------
// Kernel 3: fused pos-enc MLP + attention MLP + score + softmax + aggregate.
// One block per query point. 4 warps; warp w handles neighbors k = w, w+4, ...
// Each lane owns 4 output channels -> float4 weight loads (L1-resident weights).
// ---------------------------------------------------------------------------
__global__ void fuse_kernel(const float* __restrict__ pos,
                            const float* __restrict__ Wp1, const float* __restrict__ bp1,
                            const float* __restrict__ Wp2, const float* __restrict__ bp2,
                            const float* __restrict__ Wa1, const float* __restrict__ ba1,
                            const float* __restrict__ Wa2, const float* __restrict__ ba2,
                            const float* __restrict__ Ws,  const float* __restrict__ bs,
                            float* __restrict__ out) {
    const int row  = blockIdx.x;          // b*NPTS + i
    const int b    = row >> 12;           // NPTS = 4096
    const int tid  = threadIdx.x;
    const int lane = tid & 31;
    const int w    = tid >> 5;
    const int c4   = lane * 4;

    __shared__ float sv[KNN][COUT];       // v = feat_nb + pos_enc (for aggregation)
    __shared__ float swork[4][COUT];      // per-warp scratch: p1 / a1
    __shared__ float shh[4][COUT];        // per-warp h vector
    __shared__ float sscore[KNN];
    __shared__ float spd[KNN][3];
    __shared__ int   sidx[KNN];

    if (tid < KNN) sidx[tid] = g_idx[(size_t)row * KNN + tid];
    __syncthreads();
    if (tid < KNN * 3) {
        const int k = tid / 3;
        const int d = tid - k * 3;
        const int j = sidx[k];
        spd[k][d] = pos[(size_t)row * 3 + d] - pos[((size_t)b * NPTS + j) * 3 + d];
    }
    __syncthreads();

    const float4 fc4 = *(const float4*)(g_featc + (size_t)row * COUT + c4);
    const float4 ws4 = *(const float4*)(Ws + c4);
    const float  bsv = bs[0];

    for (int kk = 0; kk < 4; kk++) {
        const int k = w + kk * 4;
        const int j = sidx[k];
        const float d0 = spd[k][0], d1 = spd[k][1], d2 = spd[k][2];

        // p1 = relu(pos_diff @ Wp1 + bp1)
        {
            const float4 bb = *(const float4*)(bp1 + c4);
            const float4 w0 = *(const float4*)(Wp1 + c4);
            const float4 w1 = *(const float4*)(Wp1 + COUT + c4);
            const float4 w2 = *(const float4*)(Wp1 + 2 * COUT + c4);
            float4 p1;
            p1.x = fmaxf(fmaf(d0, w0.x, fmaf(d1, w1.x, fmaf(d2, w2.x, bb.x))), 0.0f);
            p1.y = fmaxf(fmaf(d0, w0.y, fmaf(d1, w1.y, fmaf(d2, w2.y, bb.y))), 0.0f);
            p1.z = fmaxf(fmaf(d0, w0.z, fmaf(d1, w1.z, fmaf(d2, w2.z, bb.z))), 0.0f);
            p1.w = fmaxf(fmaf(d0, w0.w, fmaf(d1, w1.w, fmaf(d2, w2.w, bb.w))), 0.0f);
            *(float4*)(&swork[w][c4]) = p1;
        }
        __syncwarp();

        // pos_enc = p1 @ Wp2 + bp2
        float4 pe = *(const float4*)(bp2 + c4);
        pe = dot128(pe, Wp2, &swork[w][0], c4);

        const float4 fn4 = *(const float4*)(g_featn + ((size_t)b * NPTS + j) * COUT + c4);

        float4 v4;
        v4.x = fn4.x + pe.x; v4.y = fn4.y + pe.y;
        v4.z = fn4.z + pe.z; v4.w = fn4.w + pe.w;
        *(float4*)(&sv[k][c4]) = v4;

        float4 h4;
        h4.x = fc4.x - fn4.x + pe.x; h4.y = fc4.y - fn4.y + pe.y;
        h4.z = fc4.z - fn4.z + pe.z; h4.w = fc4.w - fn4.w + pe.w;

        __syncwarp();                     // all lanes done reading swork (p1)
        *(float4*)(&shh[w][c4]) = h4;
        __syncwarp();

        // a1 = relu(h @ Wa1 + ba1)
        float4 a1 = *(const float4*)(ba1 + c4);
        a1 = dot128(a1, Wa1, &shh[w][0], c4);
        a1.x = fmaxf(a1.x, 0.0f); a1.y = fmaxf(a1.y, 0.0f);
        a1.z = fmaxf(a1.z, 0.0f); a1.w = fmaxf(a1.w, 0.0f);
        *(float4*)(&swork[w][c4]) = a1;
        __syncwarp();

        // attn = a1 @ Wa2 + ba2 ; score = attn . Ws + bs
        float4 at = *(const float4*)(ba2 + c4);
        at = dot128(at, Wa2, &swork[w][0], c4);

        float contrib = at.x * ws4.x + at.y * ws4.y + at.z * ws4.z + at.w * ws4.w;
#pragma unroll
        for (int off = 16; off > 0; off >>= 1)
            contrib += __shfl_down_sync(0xffffffffu, contrib, off);
        if (lane == 0) sscore[k] = contrib + bsv;
        __syncwarp();                     // guard swork reuse next iteration
    }

    __syncthreads();

    // softmax over k (redundant per thread) + aggregation; thread owns 1 channel
    float m = -1e30f;
#pragma unroll
    for (int k = 0; k < KNN; k++) m = fmaxf(m, sscore[k]);
    float e[KNN];
    float s = 0.0f;
#pragma unroll
    for (int k = 0; k < KNN; k++) { e[k] = expf(sscore[k] - m); s += e[k]; }
    const float inv = 1.0f / s;

    float agg = 0.0f;
#pragma unroll
    for (int k = 0; k < KNN; k++) agg = fmaf(e[k] * inv, sv[k][tid], agg);

    out[(size_t)row * COUT + tid] = g_featc[(size_t)row * COUT + tid] + agg;
}

// ---------------------------------------------------------------------------
extern "C" void kernel_launch(void* const* d_in, const int* in_sizes, int n_in,
                              void* d_out, int out_size) {
    (void)in_sizes; (void)n_in; (void)out_size;
    const float* x   = (const float*)d_in[0];
    const float* pos = (const float*)d_in[1];
    const float* Wc  = (const float*)d_in[2];
    const float* bc  = (const float*)d_in[3];
    const float* Wn  = (const float*)d_in[4];
    const float* bn  = (const float*)d_in[5];
    const float* Wp1 = (const float*)d_in[6];
    const float* bp1 = (const float*)d_in[7];
    const float* Wp2 = (const float*)d_in[8];
    const float* bp2 = (const float*)d_in[9];
    const float* Wa1 = (const float*)d_in[10];
    const float* ba1 = (const float*)d_in[11];
    const float* Wa2 = (const float*)d_in[12];
    const float* ba2 = (const float*)d_in[13];
    const float* Ws  = (const float*)d_in[14];
    const float* bs  = (const float*)d_in[15];
    float* out = (float*)d_out;

    dim3 kgrid(NPTS / 128, BATCH);
    knn_kernel<<<kgrid, 128>>>(pos);
    linear_kernel<<<BATCH * NPTS, 128>>>(x, Wc, bc, Wn, bn);
    fuse_kernel<<<BATCH * NPTS, 128>>>(pos, Wp1, bp1, Wp2, bp2,
                                       Wa1, ba1, Wa2, ba2, Ws, bs, out);
}

// round 2
// speedup vs baseline: 2.4381x; 2.4381x over previous
#include <cuda_runtime.h>

#define BATCH 4
#define NPTS  4096
#define CIN   64
#define COUT  128
#define KNN   16

// Scratch (allocation-free rule: __device__ globals)
__device__ int   g_idx[BATCH * NPTS * KNN];
__device__ float g_featc[BATCH * NPTS * COUT];
__device__ float g_featn[BATCH * NPTS * COUT];
__device__ float g_wa2ws[COUT];
__device__ float g_sconst;

// ---------------------------------------------------------------------------
// Kernel 0: fold Wa2 @ Ws and ba2 . Ws + bs  (score-path collapse)
// ---------------------------------------------------------------------------
__global__ void fold_kernel(const float* __restrict__ Wa2, const float* __restrict__ ba2,
                            const float* __restrict__ Ws,  const float* __restrict__ bs) {
    const int c = threadIdx.x;
    float s = 0.0f;
#pragma unroll 8
    for (int j = 0; j < COUT; j++) s = fmaf(Wa2[c * COUT + j], Ws[j], s);
    g_wa2ws[c] = s;
    if (c == 0) {
        float t = bs[0];
        for (int j = 0; j < COUT; j++) t = fmaf(ba2[j], Ws[j], t);
        g_sconst = t;
    }
}

// ---------------------------------------------------------------------------
// Kernel 1: brute-force KNN, candidate-split 4 ways.
// Block = 128 threads: warp w scans candidate range [w*1024,(w+1)*1024) for
// 32 queries (one per lane). Per-warp smem tiles, __syncwarp only. Then a
// 4-way sorted merge (16 of 64) per query.
// ---------------------------------------------------------------------------
__global__ void knn_kernel(const float* __restrict__ pos) {
    const int b    = blockIdx.y;
    const int lane = threadIdx.x & 31;
    const int w    = threadIdx.x >> 5;
    const int q    = blockIdx.x * 32 + lane;       // query point
    const float* posb = pos + (size_t)b * NPTS * 3;

    const float qx = posb[q * 3 + 0];
    const float qy = posb[q * 3 + 1];
    const float qz = posb[q * 3 + 2];
    const float sqq = qx * qx + qy * qy + qz * qz;

    float bd[KNN];
    int   bi[KNN];
#pragma unroll
    for (int k = 0; k < KNN; k++) { bd[k] = -1e30f; bi[k] = 0; }

    __shared__ float4 tile[4][128];                // per-warp candidate tile
    __shared__ float  sd[4][32][KNN];
    __shared__ int    si[4][32][KNN];

    const int base = w * 1024;
    for (int t = 0; t < 1024; t += 128) {
        __syncwarp();
#pragma unroll
        for (int u = 0; u < 4; u++) {
            const int j = base + t + lane * 4 + u;
            const float x = posb[j * 3 + 0];
            const float y = posb[j * 3 + 1];
            const float z = posb[j * 3 + 2];
            tile[w][lane * 4 + u] = make_float4(x, y, z, x * x + y * y + z * z);
        }
        __syncwarp();

#pragma unroll 4
        for (int jj = 0; jj < 128; jj++) {
            const float4 c = tile[w][jj];
            const float inner = qx * c.x + qy * c.y + qz * c.z;
            const float d = 2.0f * inner - sqq - c.w;
            if (d > bd[KNN - 1]) {
                bd[KNN - 1] = d;
                bi[KNN - 1] = base + t + jj;
#pragma unroll
                for (int s = KNN - 1; s > 0; --s) {
                    if (bd[s] > bd[s - 1]) {
                        const float td = bd[s]; bd[s] = bd[s - 1]; bd[s - 1] = td;
                        const int   ti = bi[s]; bi[s] = bi[s - 1]; bi[s - 1] = ti;
                    }
                }
            }
        }
    }

#pragma unroll
    for (int k = 0; k < KNN; k++) { sd[w][lane][k] = bd[k]; si[w][lane][k] = bi[k]; }
    __syncthreads();

    // 4-way merge, one thread per query (threads 0..31)
    if (threadIdx.x < 32) {
        const int t = threadIdx.x;
        int p0 = 0, p1 = 0, p2 = 0, p3 = 0;
        int* outp = g_idx + ((size_t)b * NPTS + blockIdx.x * 32 + t) * KNN;
#pragma unroll
        for (int k = 0; k < KNN; k++) {
            float bestd = -1e31f; int bests = 0, besti = 0x7fffffff;
            int pp[4] = {p0, p1, p2, p3};
#pragma unroll
            for (int s = 0; s < 4; s++) {
                if (pp[s] < KNN) {
                    const float dv = sd[s][t][pp[s]];
                    const int   iv = si[s][t][pp[s]];
                    if (dv > bestd || (dv == bestd && iv < besti)) {
                        bestd = dv; besti = iv; bests = s;
                    }
                }
            }
            outp[k] = besti;
            if (bests == 0) p0++; else if (bests == 1) p1++;
            else if (bests == 2) p2++; else p3++;
        }
    }
}

// ---------------------------------------------------------------------------
// Kernel 2: feat_c = x @ Wc + bc ; feat_n = x @ Wn + bn   (dense, pre-gather)
// ---------------------------------------------------------------------------
__global__ void linear_kernel(const float* __restrict__ x,
                              const float* __restrict__ Wc, const float* __restrict__ bc,
                              const float* __restrict__ Wn, const float* __restrict__ bn) {
    const int row = blockIdx.x;
    const int col = threadIdx.x;

    __shared__ float xs[CIN];
    if (col < CIN) xs[col] = x[(size_t)row * CIN + col];
    __syncthreads();

    float ac = bc[col];
    float an = bn[col];
#pragma unroll 8
    for (int c = 0; c < CIN; c++) {
        const float xv = xs[c];
        ac = fmaf(xv, Wc[c * COUT + col], ac);
        an = fmaf(xv, Wn[c * COUT + col], an);
    }
    g_featc[(size_t)row * COUT + col] = ac;
    g_featn[(size_t)row * COUT + col] = an;
}

// ---------------------------------------------------------------------------
// Register-tiled 16x128x128 GEMM fragment: thread owns 4 rows x 4 cols.
// A in smem [16][128] row-major (rows shared across warp -> LDS broadcast);
// W row-major [128][128] streamed from L1 as float4.
// ---------------------------------------------------------------------------
__device__ __forceinline__ void gemm_frag(const float* __restrict__ W,
                                          const float* sA, int r0, int c4,
                                          float acc[4][4]) {
#pragma unroll 8
    for (int c0 = 0; c0 < COUT; c0 += 4) {
        float4 a[4], ww[4];
#pragma unroll
        for (int i = 0; i < 4; i++) a[i] = *(const float4*)(sA + (r0 + i) * COUT + c0);
#pragma unroll
        for (int k = 0; k < 4; k++) ww[k] = *(const float4*)(W + (c0 + k) * COUT + c4);
#pragma unroll
        for (int i = 0; i < 4; i++) {
            acc[i][0] = fmaf(a[i].x, ww[0].x, acc[i][0]);
            acc[i][0] = fmaf(a[i].y, ww[1].x, acc[i][0]);
            acc[i][0] = fmaf(a[i].z, ww[2].x, acc[i][0]);
            acc[i][0] = fmaf(a[i].w, ww[3].x, acc[i][0]);
            acc[i][1] = fmaf(a[i].x, ww[0].y, acc[i][1]);
            acc[i][1] = fmaf(a[i].y, ww[1].y, acc[i][1]);
            acc[i][1] = fmaf(a[i].z, ww[2].y, acc[i][1]);
            acc[i][1] = fmaf(a[i].w, ww[3].y, acc[i][1]);
            acc[i][2] = fmaf(a[i].x, ww[0].z, acc[i][2]);
            acc[i][2] = fmaf(a[i].y, ww[1].z, acc[i][2]);
            acc[i][2] = fmaf(a[i].z, ww[2].z, acc[i][2]);
            acc[i][2] = fmaf(a[i].w, ww[3].z, acc[i][2]);
            acc[i][3] = fmaf(a[i].x, ww[0].w, acc[i][3]);
            acc[i][3] = fmaf(a[i].y, ww[1].w, acc[i][3]);
            acc[i][3] = fmaf(a[i].z, ww[2].w, acc[i][3]);
            acc[i][3] = fmaf(a[i].w, ww[3].w, acc[i][3]);
        }
    }
}

// ---------------------------------------------------------------------------
// Kernel 3: fused per-point pipeline. One block = one query point.
// Phases: P1 (tiny MLP) -> GEMM1 (pos_enc) -> build h,v -> GEMM2 + folded
// score -> softmax -> aggregate.
// ---------------------------------------------------------------------------
__global__ void fuse_kernel(const float* __restrict__ pos,
                            const float* __restrict__ Wp1, const float* __restrict__ bp1,
                            const float* __restrict__ Wp2, const float* __restrict__ bp2,
                            const float* __restrict__ Wa1, const float* __restrict__ ba1,
                            float* __restrict__ out) {
    const int row  = blockIdx.x;          // b*NPTS + i
    const int b    = row >> 12;
    const int tid  = threadIdx.x;
    const int lane = tid & 31;
    const int w    = tid >> 5;
    const int r0   = w * 4;               // 4 rows (neighbors) per warp
    const int c4   = lane * 4;            // 4 cols per lane

    __shared__ float sA[KNN * COUT];      // P1, then reused for h
    __shared__ float sV[KNN * COUT];      // feat_nb + pos_enc
    __shared__ float spd[KNN][3];
    __shared__ int   sidx[KNN];
    __shared__ float sscore[KNN];

    if (tid < KNN) sidx[tid] = g_idx[(size_t)row * KNN + tid];
    __syncthreads();
    if (tid < KNN * 3) {
        const int k = tid / 3;
        const int d = tid - k * 3;
        spd[k][d] = pos[(size_t)row * 3 + d] - pos[((size_t)(b << 12) + sidx[k]) * 3 + d];
    }
    __syncthreads();

    // Phase P1: p1[r][c] = relu(pd[r] . Wp1[:,c] + bp1[c]); col = tid
    {
        const float w0 = Wp1[tid];
        const float w1 = Wp1[COUT + tid];
        const float w2 = Wp1[2 * COUT + tid];
        const float bb = bp1[tid];
#pragma unroll
        for (int r = 0; r < KNN; r++) {
            const float v = fmaf(spd[r][0], w0, fmaf(spd[r][1], w1, fmaf(spd[r][2], w2, bb)));
            sA[r * COUT + tid] = fmaxf(v, 0.0f);
        }
    }
    __syncthreads();

    // GEMM1: pe = P1 @ Wp2 + bp2 (kept in registers)
    float acc[4][4];
    {
        const float4 b4 = *(const float4*)(bp2 + c4);
#pragma unroll
        for (int i = 0; i < 4; i++) {
            acc[i][0] = b4.x; acc[i][1] = b4.y; acc[i][2] = b4.z; acc[i][3] = b4.w;
        }
        gemm_frag(Wp2, sA, r0, c4, acc);
    }
    __syncthreads();                       // everyone done reading sA (P1)

    // Build v = fn + pe (smem), h = fc - fn + pe (into sA)
    {
        const float4 fc4 = *(const float4*)(g_featc + (size_t)row * COUT + c4);
#pragma unroll
        for (int i = 0; i < 4; i++) {
            const int r = r0 + i;
            const int j = sidx[r];
            const float4 fn = *(const float4*)(g_featn + ((size_t)(b << 12) + j) * COUT + c4);
            float4 v, h;
            v.x = fn.x + acc[i][0]; h.x = fc4.x - fn.x + acc[i][0];
            v.y = fn.y + acc[i][1]; h.y = fc4.y - fn.y + acc[i][1];
            v.z = fn.z + acc[i][2]; h.z = fc4.z - fn.z + acc[i][2];
            v.w = fn.w + acc[i][3]; h.w = fc4.w - fn.w + acc[i][3];
            *(float4*)(sV + r * COUT + c4) = v;
            *(float4*)(sA + r * COUT + c4) = h;
        }
    }
    __syncthreads();

    // GEMM2: a1 = relu(h @ Wa1 + ba1); score = a1 . (Wa2@Ws) + const
    {
        const float4 b4 = *(const float4*)(ba1 + c4);
#pragma unroll
        for (int i = 0; i < 4; i++) {
            acc[i][0] = b4.x; acc[i][1] = b4.y; acc[i][2] = b4.z; acc[i][3] = b4.w;
        }
        gemm_frag(Wa1, sA, r0, c4, acc);

        const float4 wv = *(const float4*)(g_wa2ws + c4);
        const float  sc = g_sconst;
#pragma unroll
        for (int i = 0; i < 4; i++) {
            float p = fmaxf(acc[i][0], 0.0f) * wv.x
                    + fmaxf(acc[i][1], 0.0f) * wv.y
                    + fmaxf(acc[i][2], 0.0f) * wv.z
                    + fmaxf(acc[i][3], 0.0f) * wv.w;
#pragma unroll
            for (int off = 16; off > 0; off >>= 1)
                p += __shfl_xor_sync(0xffffffffu, p, off);
            if (lane == 0) sscore[r0 + i] = p + sc;
        }
    }
    __syncthreads();

    // Softmax over 16 neighbors (redundant per thread) + aggregation
    float m = -1e30f;
#pragma unroll
    for (int k = 0; k < KNN; k++) m = fmaxf(m, sscore[k]);
    float e[KNN];
    float s = 0.0f;
#pragma unroll
    for (int k = 0; k < KNN; k++) { e[k] = expf(sscore[k] - m); s += e[k]; }
    const float inv = 1.0f / s;

    float agg = 0.0f;
#pragma unroll
    for (int k = 0; k < KNN; k++) agg = fmaf(e[k] * inv, sV[k * COUT + tid], agg);

    out[(size_t)row * COUT + tid] = g_featc[(size_t)row * COUT + tid] + agg;
}

// ---------------------------------------------------------------------------
extern "C" void kernel_launch(void* const* d_in, const int* in_sizes, int n_in,
                              void* d_out, int out_size) {
    (void)in_sizes; (void)n_in; (void)out_size;
    const float* x   = (const float*)d_in[0];
    const float* pos = (const float*)d_in[1];
    const float* Wc  = (const float*)d_in[2];
    const float* bc  = (const float*)d_in[3];
    const float* Wn  = (const float*)d_in[4];
    const float* bn  = (const float*)d_in[5];
    const float* Wp1 = (const float*)d_in[6];
    const float* bp1 = (const float*)d_in[7];
    const float* Wp2 = (const float*)d_in[8];
    const float* bp2 = (const float*)d_in[9];
    const float* Wa1 = (const float*)d_in[10];
    const float* ba1 = (const float*)d_in[11];
    const float* Wa2 = (const float*)d_in[12];
    const float* ba2 = (const float*)d_in[13];
    const float* Ws  = (const float*)d_in[14];
    const float* bs  = (const float*)d_in[15];
    float* out = (float*)d_out;

    fold_kernel<<<1, COUT>>>(Wa2, ba2, Ws, bs);
    dim3 kgrid(NPTS / 32, BATCH);
    knn_kernel<<<kgrid, 128>>>(pos);
    linear_kernel<<<BATCH * NPTS, 128>>>(x, Wc, bc, Wn, bn);
    fuse_kernel<<<BATCH * NPTS, 128>>>(pos, Wp1, bp1, Wp2, bp2, Wa1, ba1, out);
}

// round 3
// speedup vs baseline: 2.5083x; 1.0288x over previous
#include <cuda_runtime.h>

#define BATCH 4
#define NPTS  4096
#define CIN   64
#define COUT  128
#define KNN   16
#define KSPLIT 8   // knn candidate split ways

// Scratch (allocation-free rule: __device__ globals)
__device__ int   g_idx[BATCH * NPTS * KNN];
__device__ float g_featc[BATCH * NPTS * COUT];
__device__ float g_featn[BATCH * NPTS * COUT];
__device__ float g_wa2ws[COUT];
__device__ float g_sconst;

// ---------------------------------------------------------------------------
// Kernel 0: fold Wa2 @ Ws and ba2 . Ws + bs  (score-path collapse)
// ---------------------------------------------------------------------------
__global__ void fold_kernel(const float* __restrict__ Wa2, const float* __restrict__ ba2,
                            const float* __restrict__ Ws,  const float* __restrict__ bs) {
    const int c = threadIdx.x;
    float s = 0.0f;
#pragma unroll 8
    for (int j = 0; j < COUT; j++) s = fmaf(Wa2[c * COUT + j], Ws[j], s);
    g_wa2ws[c] = s;
    if (c == 0) {
        float t = bs[0];
        for (int j = 0; j < COUT; j++) t = fmaf(ba2[j], Ws[j], t);
        g_sconst = t;
    }
}

// ---------------------------------------------------------------------------
// Kernel 1: brute-force KNN, candidate-split 8 ways, 256 threads/block.
// Warp w scans [w*512,(w+1)*512) for 32 queries (one per lane).
// Ranking key: inner - 0.5*|c|^2  (monotone transform of neg squared dist;
// per-query constant sqq dropped). Batch-of-4 max-filter before insertion.
// ---------------------------------------------------------------------------
__global__ void knn_kernel(const float* __restrict__ pos) {
    const int b    = blockIdx.y;
    const int lane = threadIdx.x & 31;
    const int w    = threadIdx.x >> 5;
    const int q    = blockIdx.x * 32 + lane;       // query point
    const float* posb = pos + (size_t)b * NPTS * 3;

    const float qx = posb[q * 3 + 0];
    const float qy = posb[q * 3 + 1];
    const float qz = posb[q * 3 + 2];

    float bd[KNN];
    int   bi[KNN];
#pragma unroll
    for (int k = 0; k < KNN; k++) { bd[k] = -1e30f; bi[k] = 0; }

    __shared__ float4 tile[KSPLIT][128];           // per-warp candidate tile
    __shared__ float  sd[KSPLIT][32][KNN];
    __shared__ int    si[KSPLIT][32][KNN];

    const int base = w * (NPTS / KSPLIT);          // 512 candidates per warp
    for (int t = 0; t < NPTS / KSPLIT; t += 128) {
        __syncwarp();
#pragma unroll
        for (int u = 0; u < 4; u++) {
            const int j = base + t + lane * 4 + u;
            const float x = posb[j * 3 + 0];
            const float y = posb[j * 3 + 1];
            const float z = posb[j * 3 + 2];
            tile[w][lane * 4 + u] = make_float4(x, y, z, -0.5f * (x * x + y * y + z * z));
        }
        __syncwarp();

#pragma unroll 2
        for (int jj = 0; jj < 128; jj += 4) {
            float kk[4];
#pragma unroll
            for (int u = 0; u < 4; u++) {
                const float4 c = tile[w][jj + u];
                kk[u] = fmaf(qx, c.x, fmaf(qy, c.y, fmaf(qz, c.z, c.w)));
            }
            const float mx = fmaxf(fmaxf(kk[0], kk[1]), fmaxf(kk[2], kk[3]));
            if (mx > bd[KNN - 1]) {
#pragma unroll
                for (int u = 0; u < 4; u++) {
                    if (kk[u] > bd[KNN - 1]) {
                        bd[KNN - 1] = kk[u];
                        bi[KNN - 1] = base + t + jj + u;
#pragma unroll
                        for (int s = KNN - 1; s > 0; --s) {
                            if (bd[s] > bd[s - 1]) {
                                const float td = bd[s]; bd[s] = bd[s - 1]; bd[s - 1] = td;
                                const int   ti = bi[s]; bi[s] = bi[s - 1]; bi[s - 1] = ti;
                            }
                        }
                    }
                }
            }
        }
    }

#pragma unroll
    for (int k = 0; k < KNN; k++) { sd[w][lane][k] = bd[k]; si[w][lane][k] = bi[k]; }
    __syncthreads();

    // 8-way merge, one thread per query (threads 0..31)
    if (threadIdx.x < 32) {
        const int t = threadIdx.x;
        int pp[KSPLIT];
#pragma unroll
        for (int s = 0; s < KSPLIT; s++) pp[s] = 0;
        int* outp = g_idx + ((size_t)b * NPTS + blockIdx.x * 32 + t) * KNN;
#pragma unroll
        for (int k = 0; k < KNN; k++) {
            float bestd = -1e31f; int bests = 0, besti = 0x7fffffff;
#pragma unroll
            for (int s = 0; s < KSPLIT; s++) {
                if (pp[s] < KNN) {
                    const float dv = sd[s][t][pp[s]];
                    const int   iv = si[s][t][pp[s]];
                    if (dv > bestd || (dv == bestd && iv < besti)) {
                        bestd = dv; besti = iv; bests = s;
                    }
                }
            }
            outp[k] = besti;
            pp[bests]++;
        }
    }
}

// ---------------------------------------------------------------------------
// Kernel 2: feat_c = x @ Wc + bc ; feat_n = x @ Wn + bn   (dense, pre-gather)
// ---------------------------------------------------------------------------
__global__ void linear_kernel(const float* __restrict__ x,
                              const float* __restrict__ Wc, const float* __restrict__ bc,
                              const float* __restrict__ Wn, const float* __restrict__ bn) {
    const int row = blockIdx.x;
    const int col = threadIdx.x;

    __shared__ float xs[CIN];
    if (col < CIN) xs[col] = x[(size_t)row * CIN + col];
    __syncthreads();

    float ac = bc[col];
    float an = bn[col];
#pragma unroll 8
    for (int c = 0; c < CIN; c++) {
        const float xv = xs[c];
        ac = fmaf(xv, Wc[c * COUT + col], ac);
        an = fmaf(xv, Wn[c * COUT + col], an);
    }
    g_featc[(size_t)row * COUT + col] = ac;
    g_featn[(size_t)row * COUT + col] = an;
}

// ---------------------------------------------------------------------------
// Register-tiled GEMM fragment: thread owns 8 rows x 4 cols.
// A in smem [32][128] row-major (broadcast LDS across warp);
// W row-major [128][128] streamed from L1 as float4.
// Per k-step: 8 LDS.128 + 4 LDG.128 per 128 FFMA.
// ---------------------------------------------------------------------------
__device__ __forceinline__ void gemm_frag8(const float* __restrict__ W,
                                           const float* sA, int r0, int c4,
                                           float acc[8][4]) {
#pragma unroll 4
    for (int c0 = 0; c0 < COUT; c0 += 4) {
        float4 ww[4];
#pragma unroll
        for (int k = 0; k < 4; k++) ww[k] = *(const float4*)(W + (c0 + k) * COUT + c4);
#pragma unroll
        for (int i = 0; i < 8; i++) {
            const float4 a = *(const float4*)(sA + (r0 + i) * COUT + c0);
            acc[i][0] = fmaf(a.x, ww[0].x, acc[i][0]);
            acc[i][0] = fmaf(a.y, ww[1].x, acc[i][0]);
            acc[i][0] = fmaf(a.z, ww[2].x, acc[i][0]);
            acc[i][0] = fmaf(a.w, ww[3].x, acc[i][0]);
            acc[i][1] = fmaf(a.x, ww[0].y, acc[i][1]);
            acc[i][1] = fmaf(a.y, ww[1].y, acc[i][1]);
            acc[i][1] = fmaf(a.z, ww[2].y, acc[i][1]);
            acc[i][1] = fmaf(a.w, ww[3].y, acc[i][1]);
            acc[i][2] = fmaf(a.x, ww[0].z, acc[i][2]);
            acc[i][2] = fmaf(a.y, ww[1].z, acc[i][2]);
            acc[i][2] = fmaf(a.z, ww[2].z, acc[i][2]);
            acc[i][2] = fmaf(a.w, ww[3].z, acc[i][2]);
            acc[i][3] = fmaf(a.x, ww[0].w, acc[i][3]);
            acc[i][3] = fmaf(a.y, ww[1].w, acc[i][3]);
            acc[i][3] = fmaf(a.z, ww[2].w, acc[i][3]);
            acc[i][3] = fmaf(a.w, ww[3].w, acc[i][3]);
        }
    }
}

// ---------------------------------------------------------------------------
// Kernel 3: fused per-point pipeline. One block = TWO query points (32 rows).
// 4 warps; warp w owns rows 8w..8w+7 (warps 0-1 -> point 0, warps 2-3 -> pt 1).
// ---------------------------------------------------------------------------
__global__ void __launch_bounds__(128)
fuse_kernel(const float* __restrict__ pos,
            const float* __restrict__ Wp1, const float* __restrict__ bp1,
            const float* __restrict__ Wp2, const float* __restrict__ bp2,
            const float* __restrict__ Wa1, const float* __restrict__ ba1,
            float* __restrict__ out) {
    const int row0 = blockIdx.x * 2;      // first of two points
    const int b    = row0 >> 12;
    const int tid  = threadIdx.x;
    const int lane = tid & 31;
    const int w    = tid >> 5;
    const int r0   = w * 8;               // 8 rows per warp
    const int pw   = w >> 1;              // point handled by this warp
    const int NR   = 2 * KNN;             // 32 rows

    __shared__ float sA[32 * COUT];       // P1, then reused for h
    __shared__ float sV[32 * COUT];       // feat_nb + pos_enc
    __shared__ float spd[32][3];
    __shared__ int   sidx[32];
    __shared__ float sscore[32];

    if (tid < NR) sidx[tid] = g_idx[(size_t)row0 * KNN + tid];
    __syncthreads();
    if (tid < NR * 3) {
        const int r = tid / 3;
        const int d = tid - r * 3;
        const int p = r >> 4;
        spd[r][d] = pos[(size_t)(row0 + p) * 3 + d]
                  - pos[((size_t)(b << 12) + sidx[r]) * 3 + d];
    }
    __syncthreads();

    // Phase P1: p1[r][c] = relu(pd[r] . Wp1[:,c] + bp1[c]); col = tid
    {
        const float w0 = Wp1[tid];
        const float w1 = Wp1[COUT + tid];
        const float w2 = Wp1[2 * COUT + tid];
        const float bb = bp1[tid];
#pragma unroll
        for (int r = 0; r < NR; r++) {
            const float v = fmaf(spd[r][0], w0, fmaf(spd[r][1], w1, fmaf(spd[r][2], w2, bb)));
            sA[r * COUT + tid] = fmaxf(v, 0.0f);
        }
    }
    __syncthreads();

    const int c4 = lane * 4;

    // GEMM1: pe = P1 @ Wp2 + bp2 (kept in registers)
    float acc[8][4];
    {
        const float4 b4 = *(const float4*)(bp2 + c4);
#pragma unroll
        for (int i = 0; i < 8; i++) {
            acc[i][0] = b4.x; acc[i][1] = b4.y; acc[i][2] = b4.z; acc[i][3] = b4.w;
        }
        gemm_frag8(Wp2, sA, r0, c4, acc);
    }
    __syncthreads();                       // everyone done reading sA (P1)

    // Build v = fn + pe (smem), h = fc - fn + pe (into sA)
    {
        const float4 fc4 = *(const float4*)(g_featc + (size_t)(row0 + pw) * COUT + c4);
#pragma unroll
        for (int i = 0; i < 8; i++) {
            const int r = r0 + i;
            const int j = sidx[r];
            const float4 fn = *(const float4*)(g_featn + ((size_t)(b << 12) + j) * COUT + c4);
            float4 v, h;
            v.x = fn.x + acc[i][0]; h.x = fc4.x - fn.x + acc[i][0];
            v.y = fn.y + acc[i][1]; h.y = fc4.y - fn.y + acc[i][1];
            v.z = fn.z + acc[i][2]; h.z = fc4.z - fn.z + acc[i][2];
            v.w = fn.w + acc[i][3]; h.w = fc4.w - fn.w + acc[i][3];
            *(float4*)(sV + r * COUT + c4) = v;
            *(float4*)(sA + r * COUT + c4) = h;
        }
    }
    __syncthreads();

    // GEMM2: a1 = relu(h @ Wa1 + ba1); score = a1 . (Wa2@Ws) + const
    {
        const float4 b4 = *(const float4*)(ba1 + c4);
#pragma unroll
        for (int i = 0; i < 8; i++) {
            acc[i][0] = b4.x; acc[i][1] = b4.y; acc[i][2] = b4.z; acc[i][3] = b4.w;
        }
        gemm_frag8(Wa1, sA, r0, c4, acc);

        const float4 wv = *(const float4*)(g_wa2ws + c4);
        const float  sc = g_sconst;
#pragma unroll
        for (int i = 0; i < 8; i++) {
            float p = fmaxf(acc[i][0], 0.0f) * wv.x
                    + fmaxf(acc[i][1], 0.0f) * wv.y
                    + fmaxf(acc[i][2], 0.0f) * wv.z
                    + fmaxf(acc[i][3], 0.0f) * wv.w;
#pragma unroll
            for (int off = 16; off > 0; off >>= 1)
                p += __shfl_xor_sync(0xffffffffu, p, off);
            if (lane == 0) sscore[r0 + i] = p + sc;
        }
    }
    __syncthreads();

    // Softmax over 16 neighbors + aggregation, for both points
#pragma unroll
    for (int p = 0; p < 2; p++) {
        const float* sc = sscore + p * KNN;
        float m = -1e30f;
#pragma unroll
        for (int k = 0; k < KNN; k++) m = fmaxf(m, sc[k]);
        float e[KNN];
        float s = 0.0f;
#pragma unroll
        for (int k = 0; k < KNN; k++) { e[k] = expf(sc[k] - m); s += e[k]; }
        const float inv = 1.0f / s;

        float agg = 0.0f;
#pragma unroll
        for (int k = 0; k < KNN; k++)
            agg = fmaf(e[k] * inv, sV[(p * KNN + k) * COUT + tid], agg);

        out[(size_t)(row0 + p) * COUT + tid] =
            g_featc[(size_t)(row0 + p) * COUT + tid] + agg;
    }
}

// ---------------------------------------------------------------------------
extern "C" void kernel_launch(void* const* d_in, const int* in_sizes, int n_in,
                              void* d_out, int out_size) {
    (void)in_sizes; (void)n_in; (void)out_size;
    const float* x   = (const float*)d_in[0];
    const float* pos = (const float*)d_in[1];
    const float* Wc  = (const float*)d_in[2];
    const float* bc  = (const float*)d_in[3];
    const float* Wn  = (const float*)d_in[4];
    const float* bn  = (const float*)d_in[5];
    const float* Wp1 = (const float*)d_in[6];
    const float* bp1 = (const float*)d_in[7];
    const float* Wp2 = (const float*)d_in[8];
    const float* bp2 = (const float*)d_in[9];
    const float* Wa1 = (const float*)d_in[10];
    const float* ba1 = (const float*)d_in[11];
    const float* Wa2 = (const float*)d_in[12];
    const float* ba2 = (const float*)d_in[13];
    const float* Ws  = (const float*)d_in[14];
    const float* bs  = (const float*)d_in[15];
    float* out = (float*)d_out;

    fold_kernel<<<1, COUT>>>(Wa2, ba2, Ws, bs);
    dim3 kgrid(NPTS / 32, BATCH);
    knn_kernel<<<kgrid, 32 * KSPLIT>>>(pos);
    linear_kernel<<<BATCH * NPTS, 128>>>(x, Wc, bc, Wn, bn);
    fuse_kernel<<<BATCH * NPTS / 2, 128>>>(pos, Wp1, bp1, Wp2, bp2, Wa1, ba1, out);
}

// round 4
// speedup vs baseline: 2.9150x; 1.1622x over previous
#include <cuda_runtime.h>

#define BATCH 4
#define NPTS  4096
#define CIN   64
#define COUT  128
#define KNN   16
#define KSPLIT 4   // knn candidate split ways

typedef unsigned long long u64;

// Scratch (allocation-free rule: __device__ globals)
__device__ int   g_idx[BATCH * NPTS * KNN];
__device__ float g_featc[BATCH * NPTS * COUT];
__device__ float g_featn[BATCH * NPTS * COUT];
__device__ float g_wa2ws[COUT];
__device__ float g_sconst;

// ---- packed f32x2 helpers ---------------------------------------------------
__device__ __forceinline__ u64 pk2(float lo, float hi) {
    u64 r; asm("mov.b64 %0, {%1, %2};" : "=l"(r) : "f"(lo), "f"(hi)); return r;
}
__device__ __forceinline__ void upk2(u64 v, float& lo, float& hi) {
    asm("mov.b64 {%0, %1}, %2;" : "=f"(lo), "=f"(hi) : "l"(v));
}
__device__ __forceinline__ u64 fma2(u64 a, u64 b, u64 c) {
    u64 d; asm("fma.rn.f32x2 %0, %1, %2, %3;" : "=l"(d) : "l"(a), "l"(b), "l"(c));
    return d;
}

// ---------------------------------------------------------------------------
// Kernel 0: fold Wa2 @ Ws and ba2 . Ws + bs  (score-path collapse)
// ---------------------------------------------------------------------------
__global__ void fold_kernel(const float* __restrict__ Wa2, const float* __restrict__ ba2,
                            const float* __restrict__ Ws,  const float* __restrict__ bs) {
    const int c = threadIdx.x;
    float s = 0.0f;
#pragma unroll 8
    for (int j = 0; j < COUT; j++) s = fmaf(Wa2[c * COUT + j], Ws[j], s);
    g_wa2ws[c] = s;
    if (c == 0) {
        float t = bs[0];
        for (int j = 0; j < COUT; j++) t = fmaf(ba2[j], Ws[j], t);
        g_sconst = t;
    }
}

// ---------------------------------------------------------------------------
// Kernel 1: brute-force KNN, 4-way candidate split, 128 threads/block.
// Warp w scans [w*1024,(w+1)*1024) for 32 queries (one per lane).
// Ranking key: inner - 0.5*|c|^2 ; batch-of-4 max-filter before insertion.
// ---------------------------------------------------------------------------
__global__ void knn_kernel(const float* __restrict__ pos) {
    const int b    = blockIdx.y;
    const int lane = threadIdx.x & 31;
    const int w    = threadIdx.x >> 5;
    const int q    = blockIdx.x * 32 + lane;       // query point
    const float* posb = pos + (size_t)b * NPTS * 3;

    const float qx = posb[q * 3 + 0];
    const float qy = posb[q * 3 + 1];
    const float qz = posb[q * 3 + 2];

    float bd[KNN];
    int   bi[KNN];
#pragma unroll
    for (int k = 0; k < KNN; k++) { bd[k] = -1e30f; bi[k] = 0; }

    __shared__ float4 tile[KSPLIT][128];           // per-warp candidate tile
    __shared__ float  sd[KSPLIT][32][KNN];
    __shared__ int    si[KSPLIT][32][KNN];

    const int base = w * (NPTS / KSPLIT);          // 1024 candidates per warp
    for (int t = 0; t < NPTS / KSPLIT; t += 128) {
        __syncwarp();
#pragma unroll
        for (int u = 0; u < 4; u++) {
            const int j = base + t + lane * 4 + u;
            const float x = posb[j * 3 + 0];
            const float y = posb[j * 3 + 1];
            const float z = posb[j * 3 + 2];
            tile[w][lane * 4 + u] = make_float4(x, y, z, -0.5f * (x * x + y * y + z * z));
        }
        __syncwarp();

#pragma unroll 2
        for (int jj = 0; jj < 128; jj += 4) {
            float kk[4];
#pragma unroll
            for (int u = 0; u < 4; u++) {
                const float4 c = tile[w][jj + u];
                kk[u] = fmaf(qx, c.x, fmaf(qy, c.y, fmaf(qz, c.z, c.w)));
            }
            const float mx = fmaxf(fmaxf(kk[0], kk[1]), fmaxf(kk[2], kk[3]));
            if (mx > bd[KNN - 1]) {
#pragma unroll
                for (int u = 0; u < 4; u++) {
                    if (kk[u] > bd[KNN - 1]) {
                        bd[KNN - 1] = kk[u];
                        bi[KNN - 1] = base + t + jj + u;
#pragma unroll
                        for (int s = KNN - 1; s > 0; --s) {
                            if (bd[s] > bd[s - 1]) {
                                const float td = bd[s]; bd[s] = bd[s - 1]; bd[s - 1] = td;
                                const int   ti = bi[s]; bi[s] = bi[s - 1]; bi[s - 1] = ti;
                            }
                        }
                    }
                }
            }
        }
    }

#pragma unroll
    for (int k = 0; k < KNN; k++) { sd[w][lane][k] = bd[k]; si[w][lane][k] = bi[k]; }
    __syncthreads();

    // 4-way merge, one thread per query (threads 0..31)
    if (threadIdx.x < 32) {
        const int t = threadIdx.x;
        int pp[KSPLIT];
#pragma unroll
        for (int s = 0; s < KSPLIT; s++) pp[s] = 0;
        int* outp = g_idx + ((size_t)b * NPTS + blockIdx.x * 32 + t) * KNN;
#pragma unroll
        for (int k = 0; k < KNN; k++) {
            float bestd = -1e31f; int bests = 0, besti = 0x7fffffff;
#pragma unroll
            for (int s = 0; s < KSPLIT; s++) {
                if (pp[s] < KNN) {
                    const float dv = sd[s][t][pp[s]];
                    const int   iv = si[s][t][pp[s]];
                    if (dv > bestd || (dv == bestd && iv < besti)) {
                        bestd = dv; besti = iv; bests = s;
                    }
                }
            }
            outp[k] = besti;
            pp[bests]++;
        }
    }
}

// ---------------------------------------------------------------------------
// Kernel 2: feat_c = x @ Wc + bc ; feat_n = x @ Wn + bn  (tiled GEMM)
// Block = 32 rows, 128 threads. Warp owns 8 rows, lane owns 4 cols.
// Two passes (Wc then Wn) to bound register pressure.
// ---------------------------------------------------------------------------
__global__ void __launch_bounds__(128)
linear_kernel(const float* __restrict__ x,
              const float* __restrict__ Wc, const float* __restrict__ bc,
              const float* __restrict__ Wn, const float* __restrict__ bn) {
    const int row0 = blockIdx.x * 32;
    const int tid  = threadIdx.x;
    const int lane = tid & 31;
    const int w    = tid >> 5;
    const int r0   = w * 8;
    const int c4   = lane * 4;

    __shared__ float xs[32 * CIN];
    {
        const float4* src = (const float4*)(x + (size_t)row0 * CIN);
        float4* dst = (float4*)xs;
#pragma unroll
        for (int i = 0; i < 4; i++) dst[tid + i * 128] = src[tid + i * 128];
    }
    __syncthreads();

#pragma unroll
    for (int pass = 0; pass < 2; pass++) {
        const float* W  = pass ? Wn : Wc;
        const float* bb = pass ? bn : bc;
        float* G = pass ? g_featn : g_featc;

        float acc[8][4];
        const float4 b4 = *(const float4*)(bb + c4);
#pragma unroll
        for (int i = 0; i < 8; i++) {
            acc[i][0] = b4.x; acc[i][1] = b4.y; acc[i][2] = b4.z; acc[i][3] = b4.w;
        }

#pragma unroll 4
        for (int k0 = 0; k0 < CIN; k0 += 4) {
            float4 ww[4];
#pragma unroll
            for (int kk = 0; kk < 4; kk++)
                ww[kk] = *(const float4*)(W + (k0 + kk) * COUT + c4);
#pragma unroll
            for (int i = 0; i < 8; i++) {
                const float4 a = *(const float4*)(xs + (r0 + i) * CIN + k0);
                acc[i][0] = fmaf(a.x, ww[0].x, acc[i][0]);
                acc[i][0] = fmaf(a.y, ww[1].x, acc[i][0]);
                acc[i][0] = fmaf(a.z, ww[2].x, acc[i][0]);
                acc[i][0] = fmaf(a.w, ww[3].x, acc[i][0]);
                acc[i][1] = fmaf(a.x, ww[0].y, acc[i][1]);
                acc[i][1] = fmaf(a.y, ww[1].y, acc[i][1]);
                acc[i][1] = fmaf(a.z, ww[2].y, acc[i][1]);
                acc[i][1] = fmaf(a.w, ww[3].y, acc[i][1]);
                acc[i][2] = fmaf(a.x, ww[0].z, acc[i][2]);
                acc[i][2] = fmaf(a.y, ww[1].z, acc[i][2]);
                acc[i][2] = fmaf(a.z, ww[2].z, acc[i][2]);
                acc[i][2] = fmaf(a.w, ww[3].z, acc[i][2]);
                acc[i][3] = fmaf(a.x, ww[0].w, acc[i][3]);
                acc[i][3] = fmaf(a.y, ww[1].w, acc[i][3]);
                acc[i][3] = fmaf(a.z, ww[2].w, acc[i][3]);
                acc[i][3] = fmaf(a.w, ww[3].w, acc[i][3]);
            }
        }
#pragma unroll
        for (int i = 0; i < 8; i++) {
            float4 o; o.x = acc[i][0]; o.y = acc[i][1]; o.z = acc[i][2]; o.w = acc[i][3];
            *(float4*)(G + (size_t)(row0 + r0 + i) * COUT + c4) = o;
        }
    }
}

// ---------------------------------------------------------------------------
// Register-tiled GEMM fragment with packed f32x2 FMAs.
// Thread owns 8 rows x 4 cols; acc as col-pairs (u64). W float4 loads
// reinterpret to packed pairs for free; A scalars duplicated via mov.b64.
// Per k-step: 8 LDS.128 + 4 LDG.128 + 32 mov(alu) + 64 FFMA2 (=128 FMA).
// ---------------------------------------------------------------------------
__device__ __forceinline__ void gemm_frag8_x2(const float* __restrict__ W,
                                              const float* sA, int r0, int c4,
                                              u64 acc[8][2]) {
#pragma unroll 4
    for (int k0 = 0; k0 < COUT; k0 += 4) {
        u64 wp[4][2];
#pragma unroll
        for (int kk = 0; kk < 4; kk++) {
            const ulonglong2 t = *(const ulonglong2*)(W + (k0 + kk) * COUT + c4);
            wp[kk][0] = t.x; wp[kk][1] = t.y;
        }
#pragma unroll
        for (int i = 0; i < 8; i++) {
            const float4 a = *(const float4*)(sA + (r0 + i) * COUT + k0);
            const u64 a0 = pk2(a.x, a.x);
            const u64 a1 = pk2(a.y, a.y);
            const u64 a2 = pk2(a.z, a.z);
            const u64 a3 = pk2(a.w, a.w);
            acc[i][0] = fma2(a0, wp[0][0], acc[i][0]);
            acc[i][0] = fma2(a1, wp[1][0], acc[i][0]);
            acc[i][0] = fma2(a2, wp[2][0], acc[i][0]);
            acc[i][0] = fma2(a3, wp[3][0], acc[i][0]);
            acc[i][1] = fma2(a0, wp[0][1], acc[i][1]);
            acc[i][1] = fma2(a1, wp[1][1], acc[i][1]);
            acc[i][1] = fma2(a2, wp[2][1], acc[i][1]);
            acc[i][1] = fma2(a3, wp[3][1], acc[i][1]);
        }
    }
}

// ---------------------------------------------------------------------------
// Kernel 3: fused per-point pipeline. One block = TWO query points (32 rows).
// 4 warps; warp w owns rows 8w..8w+7 (warps 0-1 -> point 0, warps 2-3 -> pt 1).
// ---------------------------------------------------------------------------
__global__ void __launch_bounds__(128)
fuse_kernel(const float* __restrict__ pos,
            const float* __restrict__ Wp1, const float* __restrict__ bp1,
            const float* __restrict__ Wp2, const float* __restrict__ bp2,
            const float* __restrict__ Wa1, const float* __restrict__ ba1,
            float* __restrict__ out) {
    const int row0 = blockIdx.x * 2;      // first of two points
    const int b    = row0 >> 12;
    const int tid  = threadIdx.x;
    const int lane = tid & 31;
    const int w    = tid >> 5;
    const int r0   = w * 8;               // 8 rows per warp
    const int pw   = w >> 1;              // point handled by this warp
    const int NR   = 2 * KNN;             // 32 rows

    __shared__ float sA[32 * COUT];       // P1, then reused for h
    __shared__ float sV[32 * COUT];       // feat_nb + pos_enc
    __shared__ float spd[32][3];
    __shared__ int   sidx[32];
    __shared__ float sscore[32];

    if (tid < NR) sidx[tid] = g_idx[(size_t)row0 * KNN + tid];
    __syncthreads();
    if (tid < NR * 3) {
        const int r = tid / 3;
        const int d = tid - r * 3;
        const int p = r >> 4;
        spd[r][d] = pos[(size_t)(row0 + p) * 3 + d]
                  - pos[((size_t)(b << 12) + sidx[r]) * 3 + d];
    }
    __syncthreads();

    // Phase P1: p1[r][c] = relu(pd[r] . Wp1[:,c] + bp1[c]); col = tid
    {
        const float w0 = Wp1[tid];
        const float w1 = Wp1[COUT + tid];
        const float w2 = Wp1[2 * COUT + tid];
        const float bb = bp1[tid];
#pragma unroll
        for (int r = 0; r < NR; r++) {
            const float v = fmaf(spd[r][0], w0, fmaf(spd[r][1], w1, fmaf(spd[r][2], w2, bb)));
            sA[r * COUT + tid] = fmaxf(v, 0.0f);
        }
    }
    __syncthreads();

    const int c4 = lane * 4;

    // GEMM1: pe = P1 @ Wp2 + bp2 (kept in packed registers)
    u64 acc[8][2];
    {
        const float4 b4 = *(const float4*)(bp2 + c4);
        const u64 bl = pk2(b4.x, b4.y);
        const u64 bh = pk2(b4.z, b4.w);
#pragma unroll
        for (int i = 0; i < 8; i++) { acc[i][0] = bl; acc[i][1] = bh; }
        gemm_frag8_x2(Wp2, sA, r0, c4, acc);
    }
    __syncthreads();                       // everyone done reading sA (P1)

    // Build v = fn + pe (smem), h = fc - fn + pe (into sA)
    {
        const float4 fc4 = *(const float4*)(g_featc + (size_t)(row0 + pw) * COUT + c4);
#pragma unroll
        for (int i = 0; i < 8; i++) {
            const int r = r0 + i;
            const int j = sidx[r];
            const float4 fn = *(const float4*)(g_featn + ((size_t)(b << 12) + j) * COUT + c4);
            float p0, p1, p2, p3;
            upk2(acc[i][0], p0, p1);
            upk2(acc[i][1], p2, p3);
            float4 v, h;
            v.x = fn.x + p0; h.x = fc4.x - fn.x + p0;
            v.y = fn.y + p1; h.y = fc4.y - fn.y + p1;
            v.z = fn.z + p2; h.z = fc4.z - fn.z + p2;
            v.w = fn.w + p3; h.w = fc4.w - fn.w + p3;
            *(float4*)(sV + r * COUT + c4) = v;
            *(float4*)(sA + r * COUT + c4) = h;
        }
    }
    __syncthreads();

    // GEMM2: a1 = relu(h @ Wa1 + ba1); score = a1 . (Wa2@Ws) + const
    {
        const float4 b4 = *(const float4*)(ba1 + c4);
        const u64 bl = pk2(b4.x, b4.y);
        const u64 bh = pk2(b4.z, b4.w);
#pragma unroll
        for (int i = 0; i < 8; i++) { acc[i][0] = bl; acc[i][1] = bh; }
        gemm_frag8_x2(Wa1, sA, r0, c4, acc);

        const float4 wv = *(const float4*)(g_wa2ws + c4);
        const float  sc = g_sconst;
#pragma unroll
        for (int i = 0; i < 8; i++) {
            float a0, a1v, a2, a3;
            upk2(acc[i][0], a0, a1v);
            upk2(acc[i][1], a2, a3);
            float p = fmaxf(a0, 0.0f) * wv.x
                    + fmaxf(a1v, 0.0f) * wv.y
                    + fmaxf(a2, 0.0f) * wv.z
                    + fmaxf(a3, 0.0f) * wv.w;
#pragma unroll
            for (int off = 16; off > 0; off >>= 1)
                p += __shfl_xor_sync(0xffffffffu, p, off);
            if (lane == 0) sscore[r0 + i] = p + sc;
        }
    }
    __syncthreads();

    // Softmax over 16 neighbors + aggregation, for both points
#pragma unroll
    for (int p = 0; p < 2; p++) {
        const float* sc = sscore + p * KNN;
        float m = -1e30f;
#pragma unroll
        for (int k = 0; k < KNN; k++) m = fmaxf(m, sc[k]);
        float e[KNN];
        float s = 0.0f;
#pragma unroll
        for (int k = 0; k < KNN; k++) { e[k] = expf(sc[k] - m); s += e[k]; }
        const float inv = 1.0f / s;

        float agg = 0.0f;
#pragma unroll
        for (int k = 0; k < KNN; k++)
            agg = fmaf(e[k] * inv, sV[(p * KNN + k) * COUT + tid], agg);

        out[(size_t)(row0 + p) * COUT + tid] =
            g_featc[(size_t)(row0 + p) * COUT + tid] + agg;
    }
}

// ---------------------------------------------------------------------------
extern "C" void kernel_launch(void* const* d_in, const int* in_sizes, int n_in,
                              void* d_out, int out_size) {
    (void)in_sizes; (void)n_in; (void)out_size;
    const float* x   = (const float*)d_in[0];
    const float* pos = (const float*)d_in[1];
    const float* Wc  = (const float*)d_in[2];
    const float* bc  = (const float*)d_in[3];
    const float* Wn  = (const float*)d_in[4];
    const float* bn  = (const float*)d_in[5];
    const float* Wp1 = (const float*)d_in[6];
    const float* bp1 = (const float*)d_in[7];
    const float* Wp2 = (const float*)d_in[8];
    const float* bp2 = (const float*)d_in[9];
    const float* Wa1 = (const float*)d_in[10];
    const float* ba1 = (const float*)d_in[11];
    const float* Wa2 = (const float*)d_in[12];
    const float* ba2 = (const float*)d_in[13];
    const float* Ws  = (const float*)d_in[14];
    const float* bs  = (const float*)d_in[15];
    float* out = (float*)d_out;

    fold_kernel<<<1, COUT>>>(Wa2, ba2, Ws, bs);
    dim3 kgrid(NPTS / 32, BATCH);
    knn_kernel<<<kgrid, 32 * KSPLIT>>>(pos);
    linear_kernel<<<BATCH * NPTS / 32, 128>>>(x, Wc, bc, Wn, bn);
    fuse_kernel<<<BATCH * NPTS / 2, 128>>>(pos, Wp1, bp1, Wp2, bp2, Wa1, ba1, out);
}

// round 7
// speedup vs baseline: 3.6445x; 1.2502x over previous
#include <cuda_runtime.h>
#include <cuda_bf16.h>
#include <cstdint>

#define BATCH 4
#define NPTS  4096
#define CIN   64
#define COUT  128
#define KNN   16
#define KSPLIT 4
#define PTSB  8            // points per fuse block
#define ROWS  128          // PTSB * KNN
#define APAD  136          // bf16 per padded A/B row (68 u32 words)
#define AW    68           // u32 words per padded row
#define VPAD  132          // floats per padded sV row

typedef unsigned long long u64;
typedef unsigned int u32;

// ---------------- device scratch (no allocations allowed) -------------------
__device__ int   g_idx[BATCH * NPTS * KNN];
__device__ float g_featc[BATCH * NPTS * COUT];
__device__ float g_featn[BATCH * NPTS * COUT];
__device__ float g_wa2ws[COUT];
// Pre-transposed, padded bf16 hi/lo images of Wp2^T and Wa1^T: [N=128][APAD]
__device__ __align__(16) __nv_bfloat16 gWp2T_hi[128 * APAD];
__device__ __align__(16) __nv_bfloat16 gWp2T_lo[128 * APAD];
__device__ __align__(16) __nv_bfloat16 gWa1T_hi[128 * APAD];
__device__ __align__(16) __nv_bfloat16 gWa1T_lo[128 * APAD];

// ---------------- mma.sync helper -------------------------------------------
__device__ __forceinline__ void mma_bf16(float* c,
                                         u32 a0, u32 a1, u32 a2, u32 a3,
                                         u32 b0, u32 b1) {
    asm volatile(
        "mma.sync.aligned.m16n8k16.row.col.f32.bf16.bf16.f32 "
        "{%0,%1,%2,%3}, {%4,%5,%6,%7}, {%8,%9}, {%0,%1,%2,%3};"
        : "+f"(c[0]), "+f"(c[1]), "+f"(c[2]), "+f"(c[3])
        : "r"(a0), "r"(a1), "r"(a2), "r"(a3), "r"(b0), "r"(b1));
}

__device__ __forceinline__ void split2(float x, float y, u32& hi, u32& lo) {
    __nv_bfloat16 hx = __float2bfloat16(x);
    __nv_bfloat16 hy = __float2bfloat16(y);
    __nv_bfloat162 hp; hp.x = hx; hp.y = hy;
    __nv_bfloat162 lp;
    lp.x = __float2bfloat16(x - __bfloat162float(hx));
    lp.y = __float2bfloat16(y - __bfloat162float(hy));
    hi = *(u32*)&hp; lo = *(u32*)&lp;
}

// 3-term hi/lo GEMM pass: warp w computes rows [16w,16w+16) x N=128 over K=128.
__device__ __forceinline__ void gemm_pass(const u32* __restrict__ sAhi,
                                          const u32* __restrict__ sAlo,
                                          const u32* __restrict__ sBhi,
                                          const u32* __restrict__ sBlo,
                                          int w, int lane, float acc[16][4]) {
    const int rr = w * 16 + (lane >> 2);
    const int cc = lane & 3;
#pragma unroll
    for (int kt = 0; kt < 8; kt++) {
        const int ab = rr * AW + kt * 8 + cc;
        const u32 ah0 = sAhi[ab],           ah1 = sAhi[ab + 8 * AW];
        const u32 ah2 = sAhi[ab + 4],       ah3 = sAhi[ab + 8 * AW + 4];
        const u32 al0 = sAlo[ab],           al1 = sAlo[ab + 8 * AW];
        const u32 al2 = sAlo[ab + 4],       al3 = sAlo[ab + 8 * AW + 4];
#pragma unroll
        for (int nt = 0; nt < 16; nt++) {
            const int bb = (nt * 8 + (lane >> 2)) * AW + kt * 8 + cc;
            const u32 bh0 = sBhi[bb], bh1 = sBhi[bb + 4];
            const u32 bl0 = sBlo[bb], bl1 = sBlo[bb + 4];
            mma_bf16(acc[nt], ah0, ah1, ah2, ah3, bh0, bh1);
            mma_bf16(acc[nt], ah0, ah1, ah2, ah3, bl0, bl1);
            mma_bf16(acc[nt], al0, al1, al2, al3, bh0, bh1);
        }
    }
}

// ---------------- SMEM layout (bytes) ---------------------------------------
#define OFF_SIDX   0
#define OFF_SPD    512
#define OFF_SFC    2048
#define OFF_BP2    6144
#define OFF_BA1    6656
#define OFF_WV     7168
#define OFF_SPART  7680
#define OFF_AHI    8192
#define OFF_ALO    43008
#define OFF_BHI    77824
#define OFF_BLO    112640
#define OFF_SV     147456
#define SMEM_TOTAL 215040
#define BTILE_BYTES 34816   // 128 * APAD * 2

// ---------------------------------------------------------------------------
// prep: wa2ws fold + build padded bf16 hi/lo W^T images
// ---------------------------------------------------------------------------
__global__ void prep_kernel(const float* __restrict__ Wp2,
                            const float* __restrict__ Wa1,
                            const float* __restrict__ Wa2,
                            const float* __restrict__ Ws) {
    const int tid = threadIdx.x;
    if (tid < COUT) {
        float s = 0.0f;
#pragma unroll 8
        for (int j = 0; j < COUT; j++) s = fmaf(Wa2[tid * COUT + j], Ws[j], s);
        g_wa2ws[tid] = s;
    }
    for (int idx = tid; idx < 128 * 128; idx += blockDim.x) {
        const int n = idx >> 7;
        const int k = idx & 127;
        const int o = n * APAD + k;
        float v = Wp2[k * 128 + n];
        __nv_bfloat16 hi = __float2bfloat16(v);
        gWp2T_hi[o] = hi;
        gWp2T_lo[o] = __float2bfloat16(v - __bfloat162float(hi));
        v = Wa1[k * 128 + n];
        hi = __float2bfloat16(v);
        gWa1T_hi[o] = hi;
        gWa1T_lo[o] = __float2bfloat16(v - __bfloat162float(hi));
    }
}

// ---------------------------------------------------------------------------
// knn (unchanged)
// ---------------------------------------------------------------------------
__global__ void knn_kernel(const float* __restrict__ pos) {
    const int b    = blockIdx.y;
    const int lane = threadIdx.x & 31;
    const int w    = threadIdx.x >> 5;
    const int q    = blockIdx.x * 32 + lane;
    const float* posb = pos + (size_t)b * NPTS * 3;

    const float qx = posb[q * 3 + 0];
    const float qy = posb[q * 3 + 1];
    const float qz = posb[q * 3 + 2];

    float bd[KNN];
    int   bi[KNN];
#pragma unroll
    for (int k = 0; k < KNN; k++) { bd[k] = -1e30f; bi[k] = 0; }

    __shared__ float4 tile[KSPLIT][128];
    __shared__ float  sd[KSPLIT][32][KNN];
    __shared__ int    si[KSPLIT][32][KNN];

    const int base = w * (NPTS / KSPLIT);
    for (int t = 0; t < NPTS / KSPLIT; t += 128) {
        __syncwarp();
#pragma unroll
        for (int u = 0; u < 4; u++) {
            const int j = base + t + lane * 4 + u;
            const float x = posb[j * 3 + 0];
            const float y = posb[j * 3 + 1];
            const float z = posb[j * 3 + 2];
            tile[w][lane * 4 + u] = make_float4(x, y, z, -0.5f * (x * x + y * y + z * z));
        }
        __syncwarp();
#pragma unroll 2
        for (int jj = 0; jj < 128; jj += 4) {
            float kk[4];
#pragma unroll
            for (int u = 0; u < 4; u++) {
                const float4 c = tile[w][jj + u];
                kk[u] = fmaf(qx, c.x, fmaf(qy, c.y, fmaf(qz, c.z, c.w)));
            }
            const float mx = fmaxf(fmaxf(kk[0], kk[1]), fmaxf(kk[2], kk[3]));
            if (mx > bd[KNN - 1]) {
#pragma unroll
                for (int u = 0; u < 4; u++) {
                    if (kk[u] > bd[KNN - 1]) {
                        bd[KNN - 1] = kk[u];
                        bi[KNN - 1] = base + t + jj + u;
#pragma unroll
                        for (int s = KNN - 1; s > 0; --s) {
                            if (bd[s] > bd[s - 1]) {
                                const float td = bd[s]; bd[s] = bd[s - 1]; bd[s - 1] = td;
                                const int   ti = bi[s]; bi[s] = bi[s - 1]; bi[s - 1] = ti;
                            }
                        }
                    }
                }
            }
        }
    }
#pragma unroll
    for (int k = 0; k < KNN; k++) { sd[w][lane][k] = bd[k]; si[w][lane][k] = bi[k]; }
    __syncthreads();

    if (threadIdx.x < 32) {
        const int t = threadIdx.x;
        int pp[KSPLIT];
#pragma unroll
        for (int s = 0; s < KSPLIT; s++) pp[s] = 0;
        int* outp = g_idx + ((size_t)b * NPTS + blockIdx.x * 32 + t) * KNN;
#pragma unroll
        for (int k = 0; k < KNN; k++) {
            float bestd = -1e31f; int bests = 0, besti = 0x7fffffff;
#pragma unroll
            for (int s = 0; s < KSPLIT; s++) {
                if (pp[s] < KNN) {
                    const float dv = sd[s][t][pp[s]];
                    const int   iv = si[s][t][pp[s]];
                    if (dv > bestd || (dv == bestd && iv < besti)) {
                        bestd = dv; besti = iv; bests = s;
                    }
                }
            }
            outp[k] = besti;
            pp[bests]++;
        }
    }
}

// ---------------------------------------------------------------------------
// linear (unchanged): feat_c / feat_n tiled GEMM
// ---------------------------------------------------------------------------
__global__ void __launch_bounds__(128)
linear_kernel(const float* __restrict__ x,
              const float* __restrict__ Wc, const float* __restrict__ bc,
              const float* __restrict__ Wn, const float* __restrict__ bn) {
    const int row0 = blockIdx.x * 32;
    const int tid  = threadIdx.x;
    const int lane = tid & 31;
    const int w    = tid >> 5;
    const int r0   = w * 8;
    const int c4   = lane * 4;

    __shared__ float xs[32 * CIN];
    {
        const float4* src = (const float4*)(x + (size_t)row0 * CIN);
        float4* dst = (float4*)xs;
#pragma unroll
        for (int i = 0; i < 4; i++) dst[tid + i * 128] = src[tid + i * 128];
    }
    __syncthreads();

#pragma unroll
    for (int pass = 0; pass < 2; pass++) {
        const float* W  = pass ? Wn : Wc;
        const float* bb = pass ? bn : bc;
        float* G = pass ? g_featn : g_featc;

        float acc[8][4];
        const float4 b4 = *(const float4*)(bb + c4);
#pragma unroll
        for (int i = 0; i < 8; i++) {
            acc[i][0] = b4.x; acc[i][1] = b4.y; acc[i][2] = b4.z; acc[i][3] = b4.w;
        }
#pragma unroll 4
        for (int k0 = 0; k0 < CIN; k0 += 4) {
            float4 ww[4];
#pragma unroll
            for (int kk = 0; kk < 4; kk++)
                ww[kk] = *(const float4*)(W + (k0 + kk) * COUT + c4);
#pragma unroll
            for (int i = 0; i < 8; i++) {
                const float4 a = *(const float4*)(xs + (r0 + i) * CIN + k0);
                acc[i][0] = fmaf(a.x, ww[0].x, acc[i][0]);
                acc[i][0] = fmaf(a.y, ww[1].x, acc[i][0]);
                acc[i][0] = fmaf(a.z, ww[2].x, acc[i][0]);
                acc[i][0] = fmaf(a.w, ww[3].x, acc[i][0]);
                acc[i][1] = fmaf(a.x, ww[0].y, acc[i][1]);
                acc[i][1] = fmaf(a.y, ww[1].y, acc[i][1]);
                acc[i][1] = fmaf(a.z, ww[2].y, acc[i][1]);
                acc[i][1] = fmaf(a.w, ww[3].y, acc[i][1]);
                acc[i][2] = fmaf(a.x, ww[0].z, acc[i][2]);
                acc[i][2] = fmaf(a.y, ww[1].z, acc[i][2]);
                acc[i][2] = fmaf(a.z, ww[2].z, acc[i][2]);
                acc[i][2] = fmaf(a.w, ww[3].z, acc[i][2]);
                acc[i][3] = fmaf(a.x, ww[0].w, acc[i][3]);
                acc[i][3] = fmaf(a.y, ww[1].w, acc[i][3]);
                acc[i][3] = fmaf(a.z, ww[2].w, acc[i][3]);
                acc[i][3] = fmaf(a.w, ww[3].w, acc[i][3]);
            }
        }
#pragma unroll
        for (int i = 0; i < 8; i++) {
            float4 o; o.x = acc[i][0]; o.y = acc[i][1]; o.z = acc[i][2]; o.w = acc[i][3];
            *(float4*)(G + (size_t)(row0 + r0 + i) * COUT + c4) = o;
        }
    }
}

// ---------------------------------------------------------------------------
// fused mma.sync kernel: 8 points/block, 256 threads (8 warps).
// Warp w owns pair-rows [16w, 16w+16). GEMMs via bf16 hi/lo 3-term mma.sync.
// ---------------------------------------------------------------------------
__global__ void __launch_bounds__(256, 1)
fuse_kernel(const float* __restrict__ pos,
            const float* __restrict__ Wp1, const float* __restrict__ bp1,
            const float* __restrict__ bp2, const float* __restrict__ ba1,
            float* __restrict__ out) {
    extern __shared__ char smem[];
    const int tid  = threadIdx.x;
    const int lane = tid & 31;
    const int w    = tid >> 5;
    const int p0g  = blockIdx.x * PTSB;
    const int b    = p0g >> 12;

    int*   sidx  = (int*)(smem + OFF_SIDX);
    float* spd   = (float*)(smem + OFF_SPD);
    float* sfc   = (float*)(smem + OFF_SFC);
    float* sbp2  = (float*)(smem + OFF_BP2);
    float* sba1  = (float*)(smem + OFF_BA1);
    float* swv   = (float*)(smem + OFF_WV);
    float* spart = (float*)(smem + OFF_SPART);
    float* sV    = (float*)(smem + OFF_SV);
    u32* sAhi = (u32*)(smem + OFF_AHI);
    u32* sAlo = (u32*)(smem + OFF_ALO);
    u32* sBhi = (u32*)(smem + OFF_BHI);
    u32* sBlo = (u32*)(smem + OFF_BLO);

    // --- loads: indices, biases, fc, B = Wp2 images ------------------------
    if (tid < ROWS) sidx[tid] = g_idx[(size_t)p0g * KNN + tid];
    if (tid < COUT) {
        sbp2[tid] = bp2[tid];
        sba1[tid] = ba1[tid];
        swv[tid]  = g_wa2ws[tid];
    }
    {
        const uint4* h = (const uint4*)gWp2T_hi;
        const uint4* l = (const uint4*)gWp2T_lo;
        uint4* dh = (uint4*)sBhi;
        uint4* dl = (uint4*)sBlo;
#pragma unroll
        for (int i = 0; i < 8; i++) { dh[tid + i * 256] = h[tid + i * 256];
                                      dl[tid + i * 256] = l[tid + i * 256]; }
        if (tid < 128) { dh[tid + 2048] = h[tid + 2048];
                         dl[tid + 2048] = l[tid + 2048]; }
    }
    {
        const float4* src = (const float4*)(g_featc + (size_t)p0g * COUT);
        ((float4*)sfc)[tid] = src[tid];
    }
    __syncthreads();
    if (tid < ROWS) {
        const int r = tid;
        const int p = r >> 4;
        const int j = sidx[r];
        const float* qp = pos + (size_t)(p0g + p) * 3;
        const float* np = pos + ((size_t)(b << 12) + j) * 3;
        spd[r * 3 + 0] = qp[0] - np[0];
        spd[r * 3 + 1] = qp[1] - np[1];
        spd[r * 3 + 2] = qp[2] - np[2];
    }
    __syncthreads();

    // --- P1 = relu(spd @ Wp1 + bp1) -> sA (bf16 hi/lo, padded rows) --------
    {
        const int kp = tid & 63;                   // column pair 2kp, 2kp+1
        const float2 w0 = *(const float2*)(Wp1 + 0 * COUT + 2 * kp);
        const float2 w1 = *(const float2*)(Wp1 + 1 * COUT + 2 * kp);
        const float2 w2 = *(const float2*)(Wp1 + 2 * COUT + 2 * kp);
        const float2 bb = *(const float2*)(bp1 + 2 * kp);
        for (int r = tid >> 6; r < ROWS; r += 4) {
            const float d0 = spd[r * 3 + 0];
            const float d1 = spd[r * 3 + 1];
            const float d2 = spd[r * 3 + 2];
            float va = fmaxf(fmaf(d0, w0.x, fmaf(d1, w1.x, fmaf(d2, w2.x, bb.x))), 0.0f);
            float vb = fmaxf(fmaf(d0, w0.y, fmaf(d1, w1.y, fmaf(d2, w2.y, bb.y))), 0.0f);
            u32 hi, lo;
            split2(va, vb, hi, lo);
            sAhi[r * AW + kp] = hi;
            sAlo[r * AW + kp] = lo;
        }
    }
    __syncthreads();

    // --- GEMM1: pe_pre = P1 @ Wp2 ------------------------------------------
    float acc[16][4];
#pragma unroll
    for (int nt = 0; nt < 16; nt++) {
        acc[nt][0] = 0.f; acc[nt][1] = 0.f; acc[nt][2] = 0.f; acc[nt][3] = 0.f;
    }
    gemm_pass(sAhi, sAlo, sBhi, sBlo, w, lane, acc);

    // --- epilogue 1: v -> sV, h -> sA (warp-private rows; no sync needed) --
    {
        const int r1 = w * 16 + (lane >> 2);
        const int r2 = r1 + 8;
        const int j1 = sidx[r1], j2 = sidx[r2];
        const float* fn1 = g_featn + ((size_t)(b << 12) + j1) * COUT;
        const float* fn2 = g_featn + ((size_t)(b << 12) + j2) * COUT;
        const float* fc1 = sfc + (r1 >> 4) * COUT;
        const float* fc2 = sfc + (r2 >> 4) * COUT;
#pragma unroll
        for (int nt = 0; nt < 16; nt++) {
            const int col = nt * 8 + (lane & 3) * 2;
            const float2 bq = *(const float2*)(sbp2 + col);
            // row r1
            {
                const float2 fn = *(const float2*)(fn1 + col);
                const float2 fc = *(const float2*)(fc1 + col);
                const float pe0 = acc[nt][0] + bq.x;
                const float pe1 = acc[nt][1] + bq.y;
                float2 v; v.x = fn.x + pe0; v.y = fn.y + pe1;
                *(float2*)(sV + r1 * VPAD + col) = v;
                u32 hi, lo;
                split2(fc.x - fn.x + pe0, fc.y - fn.y + pe1, hi, lo);
                sAhi[r1 * AW + (col >> 1)] = hi;
                sAlo[r1 * AW + (col >> 1)] = lo;
            }
            // row r2
            {
                const float2 fn = *(const float2*)(fn2 + col);
                const float2 fc = *(const float2*)(fc2 + col);
                const float pe0 = acc[nt][2] + bq.x;
                const float pe1 = acc[nt][3] + bq.y;
                float2 v; v.x = fn.x + pe0; v.y = fn.y + pe1;
                *(float2*)(sV + r2 * VPAD + col) = v;
                u32 hi, lo;
                split2(fc.x - fn.x + pe0, fc.y - fn.y + pe1, hi, lo);
                sAhi[r2 * AW + (col >> 1)] = hi;
                sAlo[r2 * AW + (col >> 1)] = lo;
            }
        }
    }
    __syncthreads();                       // all warps done reading B (Wp2)

    // --- B := Wa1 images ---------------------------------------------------
    {
        const uint4* h = (const uint4*)gWa1T_hi;
        const uint4* l = (const uint4*)gWa1T_lo;
        uint4* dh = (uint4*)sBhi;
        uint4* dl = (uint4*)sBlo;
#pragma unroll
        for (int i = 0; i < 8; i++) { dh[tid + i * 256] = h[tid + i * 256];
                                      dl[tid + i * 256] = l[tid + i * 256]; }
        if (tid < 128) { dh[tid + 2048] = h[tid + 2048];
                         dl[tid + 2048] = l[tid + 2048]; }
    }
    __syncthreads();

    // --- GEMM2: a1_pre = h @ Wa1 ------------------------------------------
#pragma unroll
    for (int nt = 0; nt < 16; nt++) {
        acc[nt][0] = 0.f; acc[nt][1] = 0.f; acc[nt][2] = 0.f; acc[nt][3] = 0.f;
    }
    gemm_pass(sAhi, sAlo, sBhi, sBlo, w, lane, acc);

    // --- epilogue 2: scores ------------------------------------------------
    {
        float s1 = 0.0f, s2 = 0.0f;
#pragma unroll
        for (int nt = 0; nt < 16; nt++) {
            const int col = nt * 8 + (lane & 3) * 2;
            const float2 ba = *(const float2*)(sba1 + col);
            const float2 wv = *(const float2*)(swv + col);
            s1 = fmaf(fmaxf(acc[nt][0] + ba.x, 0.0f), wv.x, s1);
            s1 = fmaf(fmaxf(acc[nt][1] + ba.y, 0.0f), wv.y, s1);
            s2 = fmaf(fmaxf(acc[nt][2] + ba.x, 0.0f), wv.x, s2);
            s2 = fmaf(fmaxf(acc[nt][3] + ba.y, 0.0f), wv.y, s2);
        }
        s1 += __shfl_xor_sync(0xffffffffu, s1, 1);
        s1 += __shfl_xor_sync(0xffffffffu, s1, 2);
        s2 += __shfl_xor_sync(0xffffffffu, s2, 1);
        s2 += __shfl_xor_sync(0xffffffffu, s2, 2);
        if ((lane & 3) == 0) {
            const int r1 = w * 16 + (lane >> 2);
            spart[r1] = s1;
            spart[r1 + 8] = s2;
        }
    }
    __syncthreads();

    // --- softmax + aggregation --------------------------------------------
    {
        const int p  = tid >> 5;               // 0..7
        const int c4 = (tid & 31) * 4;
        float sc[KNN];
        float m = -1e30f;
#pragma unroll
        for (int k = 0; k < KNN; k++) {
            sc[k] = spart[p * KNN + k];
            m = fmaxf(m, sc[k]);
        }
        float s = 0.0f;
#pragma unroll
        for (int k = 0; k < KNN; k++) { sc[k] = expf(sc[k] - m); s += sc[k]; }
        const float inv = 1.0f / s;
        float4 agg = make_float4(0.f, 0.f, 0.f, 0.f);
#pragma unroll
        for (int k = 0; k < KNN; k++) {
            const float wk = sc[k] * inv;
            const float4 v = *(const float4*)(sV + (p * KNN + k) * VPAD + c4);
            agg.x = fmaf(wk, v.x, agg.x);
            agg.y = fmaf(wk, v.y, agg.y);
            agg.z = fmaf(wk, v.z, agg.z);
            agg.w = fmaf(wk, v.w, agg.w);
        }
        const float4 fc = *(const float4*)(sfc + p * COUT + c4);
        float4 o;
        o.x = fc.x + agg.x; o.y = fc.y + agg.y;
        o.z = fc.z + agg.z; o.w = fc.w + agg.w;
        *(float4*)(out + (size_t)(p0g + p) * COUT + c4) = o;
    }
}

// ---------------------------------------------------------------------------
extern "C" void kernel_launch(void* const* d_in, const int* in_sizes, int n_in,
                              void* d_out, int out_size) {
    (void)in_sizes; (void)n_in; (void)out_size;
    const float* x   = (const float*)d_in[0];
    const float* pos = (const float*)d_in[1];
    const float* Wc  = (const float*)d_in[2];
    const float* bc  = (const float*)d_in[3];
    const float* Wn  = (const float*)d_in[4];
    const float* bn  = (const float*)d_in[5];
    const float* Wp1 = (const float*)d_in[6];
    const float* bp1 = (const float*)d_in[7];
    const float* Wp2 = (const float*)d_in[8];
    const float* bp2 = (const float*)d_in[9];
    const float* Wa1 = (const float*)d_in[10];
    const float* ba1 = (const float*)d_in[11];
    const float* Wa2 = (const float*)d_in[12];
    const float* ba2 = (const float*)d_in[13];
    const float* Ws  = (const float*)d_in[14];
    (void)ba2;   // ba2.Ws folds to a softmax-invariant constant -> dropped
    float* out = (float*)d_out;

    cudaFuncSetAttribute(fuse_kernel, cudaFuncAttributeMaxDynamicSharedMemorySize,
                         SMEM_TOTAL);

    prep_kernel<<<1, 256>>>(Wp2, Wa1, Wa2, Ws);
    dim3 kgrid(NPTS / 32, BATCH);
    knn_kernel<<<kgrid, 32 * KSPLIT>>>(pos);
    linear_kernel<<<BATCH * NPTS / 32, 128>>>(x, Wc, bc, Wn, bn);
    fuse_kernel<<<BATCH * NPTS / PTSB, 256, SMEM_TOTAL>>>(pos, Wp1, bp1, bp2, ba1, out);
}

// round 8
// speedup vs baseline: 3.6638x; 1.0053x over previous
#include <cuda_runtime.h>
#include <cuda_bf16.h>
#include <cstdint>

#define BATCH 4
#define NPTS  4096
#define CIN   64
#define COUT  128
#define KNN   16
#define KSPLIT 4
#define PTSB  8            // points per fuse block
#define ROWS  128          // PTSB * KNN
#define APAD  136          // bf16 per padded A/B row
#define AW    68           // u32 words per padded row
#define VPAD  132          // floats per padded sV row

typedef unsigned long long u64;
typedef unsigned int u32;

// ---------------- device scratch (no allocations allowed) -------------------
__device__ int   g_idx[BATCH * NPTS * KNN];
__device__ float g_knd[2 * BATCH * NPTS * KNN];
__device__ int   g_kni[2 * BATCH * NPTS * KNN];
__device__ float g_featc[BATCH * NPTS * COUT];
__device__ float g_featn[BATCH * NPTS * COUT];
__device__ float g_wa2ws[COUT];
__device__ __align__(16) __nv_bfloat16 gWp2T_hi[128 * APAD];
__device__ __align__(16) __nv_bfloat16 gWp2T_lo[128 * APAD];
__device__ __align__(16) __nv_bfloat16 gWa1T_hi[128 * APAD];
__device__ __align__(16) __nv_bfloat16 gWa1T_lo[128 * APAD];

// ---------------- mma/ldmatrix helpers ---------------------------------------
__device__ __forceinline__ void mma_bf16(float* c,
                                         u32 a0, u32 a1, u32 a2, u32 a3,
                                         u32 b0, u32 b1) {
    asm volatile(
        "mma.sync.aligned.m16n8k16.row.col.f32.bf16.bf16.f32 "
        "{%0,%1,%2,%3}, {%4,%5,%6,%7}, {%8,%9}, {%0,%1,%2,%3};"
        : "+f"(c[0]), "+f"(c[1]), "+f"(c[2]), "+f"(c[3])
        : "r"(a0), "r"(a1), "r"(a2), "r"(a3), "r"(b0), "r"(b1));
}
__device__ __forceinline__ void ldsm_x4(u32* r, u32 addr) {
    asm volatile("ldmatrix.sync.aligned.m8n8.x4.shared.b16 {%0,%1,%2,%3}, [%4];"
        : "=r"(r[0]), "=r"(r[1]), "=r"(r[2]), "=r"(r[3]) : "r"(addr));
}
__device__ __forceinline__ u32 smem_u32(const void* p) {
    u32 a;
    asm("{ .reg .u64 t; cvta.to.shared.u64 t, %1; cvt.u32.u64 %0, t; }"
        : "=r"(a) : "l"(p));
    return a;
}
__device__ __forceinline__ void split2(float x, float y, u32& hi, u32& lo) {
    __nv_bfloat16 hx = __float2bfloat16(x);
    __nv_bfloat16 hy = __float2bfloat16(y);
    __nv_bfloat162 hp; hp.x = hx; hp.y = hy;
    __nv_bfloat162 lp;
    lp.x = __float2bfloat16(x - __bfloat162float(hx));
    lp.y = __float2bfloat16(y - __bfloat162float(hy));
    hi = *(u32*)&hp; lo = *(u32*)&lp;
}

// ---------------- SMEM layout (bytes) ---------------------------------------
#define OFF_SIDX   0
#define OFF_SPD    512
#define OFF_SFC    2048
#define OFF_BP2    6144
#define OFF_BA1    6656
#define OFF_WV     7168
#define OFF_SPART  7680
#define OFF_AHI    8704
#define OFF_ALO    43520
#define OFF_BHI    78336
#define OFF_BLO    113152
#define OFF_SV     147968
#define SMEM_TOTAL 215552
#define DLO        34816    // ALO-AHI == BLO-BHI

// ---------------------------------------------------------------------------
// prep: blocks 0..63 build W^T bf16 hi/lo images; block 64 folds Wa2@Ws.
// ---------------------------------------------------------------------------
__global__ void prep_kernel(const float* __restrict__ Wp2,
                            const float* __restrict__ Wa1,
                            const float* __restrict__ Wa2,
                            const float* __restrict__ Ws) {
    const int blk = blockIdx.x;
    const int tid = threadIdx.x;
    if (blk == 64) {
        if (tid < COUT) {
            float s = 0.0f;
#pragma unroll 8
            for (int j = 0; j < COUT; j++) s = fmaf(Wa2[tid * COUT + j], Ws[j], s);
            g_wa2ws[tid] = s;
        }
        return;
    }
    const int idx = blk * 256 + tid;       // 0..16383
    const int n = idx & 127;               // coalesced read dim
    const int k = idx >> 7;
    const int o = n * APAD + k;
    float v = Wp2[k * 128 + n];
    __nv_bfloat16 hi = __float2bfloat16(v);
    gWp2T_hi[o] = hi;
    gWp2T_lo[o] = __float2bfloat16(v - __bfloat162float(hi));
    v = Wa1[k * 128 + n];
    hi = __float2bfloat16(v);
    gWa1T_hi[o] = hi;
    gWa1T_lo[o] = __float2bfloat16(v - __bfloat162float(hi));
}

// ---------------------------------------------------------------------------
// knn: blockIdx.z = candidate half. Block scans 2048 candidates (4 warps x 512),
// writes per-half sorted top-16 (keys + indices) for later merge.
// ---------------------------------------------------------------------------
__global__ void knn_kernel(const float* __restrict__ pos) {
    const int b    = blockIdx.y;
    const int half = blockIdx.z;
    const int lane = threadIdx.x & 31;
    const int w    = threadIdx.x >> 5;
    const int q    = blockIdx.x * 32 + lane;
    const float* posb = pos + (size_t)b * NPTS * 3;

    const float qx = posb[q * 3 + 0];
    const float qy = posb[q * 3 + 1];
    const float qz = posb[q * 3 + 2];

    float bd[KNN];
    int   bi[KNN];
#pragma unroll
    for (int k = 0; k < KNN; k++) { bd[k] = -1e30f; bi[k] = 0; }

    __shared__ float4 tile[KSPLIT][128];
    __shared__ float  sd[KSPLIT][32][KNN];
    __shared__ int    si[KSPLIT][32][KNN];

    const int base = half * 2048 + w * 512;
    for (int t = 0; t < 512; t += 128) {
        __syncwarp();
#pragma unroll
        for (int u = 0; u < 4; u++) {
            const int j = base + t + lane * 4 + u;
            const float x = posb[j * 3 + 0];
            const float y = posb[j * 3 + 1];
            const float z = posb[j * 3 + 2];
            tile[w][lane * 4 + u] = make_float4(x, y, z, -0.5f * (x * x + y * y + z * z));
        }
        __syncwarp();
#pragma unroll 2
        for (int jj = 0; jj < 128; jj += 4) {
            float kk[4];
#pragma unroll
            for (int u = 0; u < 4; u++) {
                const float4 c = tile[w][jj + u];
                kk[u] = fmaf(qx, c.x, fmaf(qy, c.y, fmaf(qz, c.z, c.w)));
            }
            const float mx = fmaxf(fmaxf(kk[0], kk[1]), fmaxf(kk[2], kk[3]));
            if (mx > bd[KNN - 1]) {
#pragma unroll
                for (int u = 0; u < 4; u++) {
                    if (kk[u] > bd[KNN - 1]) {
                        bd[KNN - 1] = kk[u];
                        bi[KNN - 1] = base + t + jj + u;
#pragma unroll
                        for (int s = KNN - 1; s > 0; --s) {
                            if (bd[s] > bd[s - 1]) {
                                const float td = bd[s]; bd[s] = bd[s - 1]; bd[s - 1] = td;
                                const int   ti = bi[s]; bi[s] = bi[s - 1]; bi[s - 1] = ti;
                            }
                        }
                    }
                }
            }
        }
    }
#pragma unroll
    for (int k = 0; k < KNN; k++) { sd[w][lane][k] = bd[k]; si[w][lane][k] = bi[k]; }
    __syncthreads();

    if (threadIdx.x < 32) {
        const int t = threadIdx.x;
        int pp[KSPLIT];
#pragma unroll
        for (int s = 0; s < KSPLIT; s++) pp[s] = 0;
        const size_t qg = (size_t)b * NPTS + blockIdx.x * 32 + t;
        float* outd = g_knd + ((size_t)half * BATCH * NPTS + qg) * KNN;
        int*   outi = g_kni + ((size_t)half * BATCH * NPTS + qg) * KNN;
#pragma unroll
        for (int k = 0; k < KNN; k++) {
            float bestd = -1e31f; int bests = 0, besti = 0x7fffffff;
#pragma unroll
            for (int s = 0; s < KSPLIT; s++) {
                if (pp[s] < KNN) {
                    const float dv = sd[s][t][pp[s]];
                    const int   iv = si[s][t][pp[s]];
                    if (dv > bestd || (dv == bestd && iv < besti)) {
                        bestd = dv; besti = iv; bests = s;
                    }
                }
            }
            outd[k] = bestd; outi[k] = besti;
            pp[bests]++;
        }
    }
}

// Merge the two candidate halves' sorted lists into final g_idx.
// Half0 indices are always < half1 indices, so ties (==) take half0.
__global__ void knn_merge_kernel() {
    const size_t q = (size_t)blockIdx.x * blockDim.x + threadIdx.x;
    const float* d0 = g_knd + q * KNN;
    const float* d1 = g_knd + ((size_t)BATCH * NPTS + q) * KNN;
    const int*   i0 = g_kni + q * KNN;
    const int*   i1 = g_kni + ((size_t)BATCH * NPTS + q) * KNN;
    int p0 = 0, p1 = 0;
    int* outp = g_idx + q * KNN;
#pragma unroll
    for (int k = 0; k < KNN; k++) {
        const float a = d0[p0];
        const float c = d1[p1];
        if (a >= c) { outp[k] = i0[p0]; p0++; }
        else        { outp[k] = i1[p1]; p1++; }
    }
}

// ---------------------------------------------------------------------------
// linear (unchanged): feat_c / feat_n tiled GEMM
// ---------------------------------------------------------------------------
__global__ void __launch_bounds__(128)
linear_kernel(const float* __restrict__ x,
              const float* __restrict__ Wc, const float* __restrict__ bc,
              const float* __restrict__ Wn, const float* __restrict__ bn) {
    const int row0 = blockIdx.x * 32;
    const int tid  = threadIdx.x;
    const int lane = tid & 31;
    const int w    = tid >> 5;
    const int r0   = w * 8;
    const int c4   = lane * 4;

    __shared__ float xs[32 * CIN];
    {
        const float4* src = (const float4*)(x + (size_t)row0 * CIN);
        float4* dst = (float4*)xs;
#pragma unroll
        for (int i = 0; i < 4; i++) dst[tid + i * 128] = src[tid + i * 128];
    }
    __syncthreads();

#pragma unroll
    for (int pass = 0; pass < 2; pass++) {
        const float* W  = pass ? Wn : Wc;
        const float* bb = pass ? bn : bc;
        float* G = pass ? g_featn : g_featc;

        float acc[8][4];
        const float4 b4 = *(const float4*)(bb + c4);
#pragma unroll
        for (int i = 0; i < 8; i++) {
            acc[i][0] = b4.x; acc[i][1] = b4.y; acc[i][2] = b4.z; acc[i][3] = b4.w;
        }
#pragma unroll 4
        for (int k0 = 0; k0 < CIN; k0 += 4) {
            float4 ww[4];
#pragma unroll
            for (int kk = 0; kk < 4; kk++)
                ww[kk] = *(const float4*)(W + (k0 + kk) * COUT + c4);
#pragma unroll
            for (int i = 0; i < 8; i++) {
                const float4 a = *(const float4*)(xs + (r0 + i) * CIN + k0);
                acc[i][0] = fmaf(a.x, ww[0].x, acc[i][0]);
                acc[i][0] = fmaf(a.y, ww[1].x, acc[i][0]);
                acc[i][0] = fmaf(a.z, ww[2].x, acc[i][0]);
                acc[i][0] = fmaf(a.w, ww[3].x, acc[i][0]);
                acc[i][1] = fmaf(a.x, ww[0].y, acc[i][1]);
                acc[i][1] = fmaf(a.y, ww[1].y, acc[i][1]);
                acc[i][1] = fmaf(a.z, ww[2].y, acc[i][1]);
                acc[i][1] = fmaf(a.w, ww[3].y, acc[i][1]);
                acc[i][2] = fmaf(a.x, ww[0].z, acc[i][2]);
                acc[i][2] = fmaf(a.y, ww[1].z, acc[i][2]);
                acc[i][2] = fmaf(a.z, ww[2].z, acc[i][2]);
                acc[i][2] = fmaf(a.w, ww[3].z, acc[i][2]);
                acc[i][3] = fmaf(a.x, ww[0].w, acc[i][3]);
                acc[i][3] = fmaf(a.y, ww[1].w, acc[i][3]);
                acc[i][3] = fmaf(a.z, ww[2].w, acc[i][3]);
                acc[i][3] = fmaf(a.w, ww[3].w, acc[i][3]);
            }
        }
#pragma unroll
        for (int i = 0; i < 8; i++) {
            float4 o; o.x = acc[i][0]; o.y = acc[i][1]; o.z = acc[i][2]; o.w = acc[i][3];
            *(float4*)(G + (size_t)(row0 + r0 + i) * COUT + c4) = o;
        }
    }
}

// ---------------------------------------------------------------------------
// gemm pass: warp (wm = w&3, wn = w>>2) computes rows [32wm,32wm+32) x
// cols [64wn, 64wn+64), K=128, via ldmatrix.x4 + 3-term bf16 hi/lo mma.sync.
// ---------------------------------------------------------------------------
__device__ __forceinline__ void gemm_pass(u32 sb, int wm, int wn, int lane,
                                          float (&acc)[2][8][4]) {
    const int arow = wm * 32 + ((lane >> 3) & 1) * 8 + (lane & 7);
    const int ak   = (lane >> 4) * 8;
    u32 aB = sb + OFF_AHI + (u32)(arow * (AW * 4) + ak * 2);
    const int nrow = wn * 64 + (lane >> 4) * 8 + (lane & 7);
    const int bk   = ((lane >> 3) & 1) * 8;
    u32 bB = sb + OFF_BHI + (u32)(nrow * (AW * 4) + bk * 2);
#pragma unroll
    for (int kt = 0; kt < 8; kt++) {
        u32 ah0[4], al0[4], ah1[4], al1[4];
        ldsm_x4(ah0, aB);
        ldsm_x4(al0, aB + DLO);
        ldsm_x4(ah1, aB + 16 * (AW * 4));
        ldsm_x4(al1, aB + 16 * (AW * 4) + DLO);
#pragma unroll
        for (int p = 0; p < 4; p++) {
            u32 bh[4], bl[4];
            const u32 ba = bB + p * 16 * (AW * 4);
            ldsm_x4(bh, ba);
            ldsm_x4(bl, ba + DLO);
            mma_bf16(acc[0][2*p],   ah0[0],ah0[1],ah0[2],ah0[3], bh[0],bh[1]);
            mma_bf16(acc[0][2*p],   ah0[0],ah0[1],ah0[2],ah0[3], bl[0],bl[1]);
            mma_bf16(acc[0][2*p],   al0[0],al0[1],al0[2],al0[3], bh[0],bh[1]);
            mma_bf16(acc[0][2*p+1], ah0[0],ah0[1],ah0[2],ah0[3], bh[2],bh[3]);
            mma_bf16(acc[0][2*p+1], ah0[0],ah0[1],ah0[2],ah0[3], bl[2],bl[3]);
            mma_bf16(acc[0][2*p+1], al0[0],al0[1],al0[2],al0[3], bh[2],bh[3]);
            mma_bf16(acc[1][2*p],   ah1[0],ah1[1],ah1[2],ah1[3], bh[0],bh[1]);
            mma_bf16(acc[1][2*p],   ah1[0],ah1[1],ah1[2],ah1[3], bl[0],bl[1]);
            mma_bf16(acc[1][2*p],   al1[0],al1[1],al1[2],al1[3], bh[0],bh[1]);
            mma_bf16(acc[1][2*p+1], ah1[0],ah1[1],ah1[2],ah1[3], bh[2],bh[3]);
            mma_bf16(acc[1][2*p+1], ah1[0],ah1[1],ah1[2],ah1[3], bl[2],bl[3]);
            mma_bf16(acc[1][2*p+1], al1[0],al1[1],al1[2],al1[3], bh[2],bh[3]);
        }
        aB += 32;
        bB += 32;
    }
}

// ---------------------------------------------------------------------------
// fused kernel: 8 points/block, 256 threads (8 warps as 4M x 2N).
// ---------------------------------------------------------------------------
__global__ void __launch_bounds__(256, 1)
fuse_kernel(const float* __restrict__ pos,
            const float* __restrict__ Wp1, const float* __restrict__ bp1,
            const float* __restrict__ bp2, const float* __restrict__ ba1,
            float* __restrict__ out) {
    extern __shared__ char smem[];
    const u32 sb   = smem_u32(smem);
    const int tid  = threadIdx.x;
    const int lane = tid & 31;
    const int w    = tid >> 5;
    const int wm   = w & 3;
    const int wn   = w >> 2;
    const int p0g  = blockIdx.x * PTSB;
    const int b    = p0g >> 12;

    int*   sidx  = (int*)(smem + OFF_SIDX);
    float* spd   = (float*)(smem + OFF_SPD);
    float* sfc   = (float*)(smem + OFF_SFC);
    float* sbp2  = (float*)(smem + OFF_BP2);
    float* sba1  = (float*)(smem + OFF_BA1);
    float* swv   = (float*)(smem + OFF_WV);
    float* spart = (float*)(smem + OFF_SPART);
    float* sV    = (float*)(smem + OFF_SV);
    u32* sAhi = (u32*)(smem + OFF_AHI);
    u32* sAlo = (u32*)(smem + OFF_ALO);
    u32* sBhi = (u32*)(smem + OFF_BHI);
    u32* sBlo = (u32*)(smem + OFF_BLO);

    // --- loads -------------------------------------------------------------
    if (tid < ROWS) sidx[tid] = g_idx[(size_t)p0g * KNN + tid];
    if (tid < COUT) {
        sbp2[tid] = bp2[tid];
        sba1[tid] = ba1[tid];
        swv[tid]  = g_wa2ws[tid];
    }
    {
        const uint4* h = (const uint4*)gWp2T_hi;
        const uint4* l = (const uint4*)gWp2T_lo;
        uint4* dh = (uint4*)sBhi;
        uint4* dl = (uint4*)sBlo;
#pragma unroll
        for (int i = 0; i < 8; i++) { dh[tid + i * 256] = h[tid + i * 256];
                                      dl[tid + i * 256] = l[tid + i * 256]; }
        if (tid < 128) { dh[tid + 2048] = h[tid + 2048];
                         dl[tid + 2048] = l[tid + 2048]; }
    }
    {
        const float4* src = (const float4*)(g_featc + (size_t)p0g * COUT);
        ((float4*)sfc)[tid] = src[tid];
    }
    __syncthreads();
    if (tid < ROWS) {
        const int r = tid;
        const int p = r >> 4;
        const int j = sidx[r];
        const float* qp = pos + (size_t)(p0g + p) * 3;
        const float* np = pos + ((size_t)(b << 12) + j) * 3;
        spd[r * 3 + 0] = qp[0] - np[0];
        spd[r * 3 + 1] = qp[1] - np[1];
        spd[r * 3 + 2] = qp[2] - np[2];
    }
    __syncthreads();

    // --- P1 = relu(spd @ Wp1 + bp1) -> sA (bf16 hi/lo) ---------------------
    {
        const int kp = tid & 63;
        const float2 w0 = *(const float2*)(Wp1 + 0 * COUT + 2 * kp);
        const float2 w1 = *(const float2*)(Wp1 + 1 * COUT + 2 * kp);
        const float2 w2 = *(const float2*)(Wp1 + 2 * COUT + 2 * kp);
        const float2 bb = *(const float2*)(bp1 + 2 * kp);
        for (int r = tid >> 6; r < ROWS; r += 4) {
            const float d0 = spd[r * 3 + 0];
            const float d1 = spd[r * 3 + 1];
            const float d2 = spd[r * 3 + 2];
            float va = fmaxf(fmaf(d0, w0.x, fmaf(d1, w1.x, fmaf(d2, w2.x, bb.x))), 0.0f);
            float vb = fmaxf(fmaf(d0, w0.y, fmaf(d1, w1.y, fmaf(d2, w2.y, bb.y))), 0.0f);
            u32 hi, lo;
            split2(va, vb, hi, lo);
            sAhi[r * AW + kp] = hi;
            sAlo[r * AW + kp] = lo;
        }
    }
    __syncthreads();

    // --- GEMM1: pe_pre = P1 @ Wp2 ------------------------------------------
    float acc[2][8][4];
#pragma unroll
    for (int mt = 0; mt < 2; mt++)
#pragma unroll
        for (int nt = 0; nt < 8; nt++) {
            acc[mt][nt][0] = 0.f; acc[mt][nt][1] = 0.f;
            acc[mt][nt][2] = 0.f; acc[mt][nt][3] = 0.f;
        }
    gemm_pass(sb, wm, wn, lane, acc);
    __syncthreads();                       // all warps done reading P1 + B(Wp2)

    // --- B := Wa1 images ---------------------------------------------------
    {
        const uint4* h = (const uint4*)gWa1T_hi;
        const uint4* l = (const uint4*)gWa1T_lo;
        uint4* dh = (uint4*)sBhi;
        uint4* dl = (uint4*)sBlo;
#pragma unroll
        for (int i = 0; i < 8; i++) { dh[tid + i * 256] = h[tid + i * 256];
                                      dl[tid + i * 256] = l[tid + i * 256]; }
        if (tid < 128) { dh[tid + 2048] = h[tid + 2048];
                         dl[tid + 2048] = l[tid + 2048]; }
    }

    // --- epilogue 1: v -> sV, h -> sA --------------------------------------
#pragma unroll
    for (int mt = 0; mt < 2; mt++) {
        const int r1 = wm * 32 + mt * 16 + (lane >> 2);
        const int r2 = r1 + 8;
        const int j1 = sidx[r1], j2 = sidx[r2];
        const float* fn1 = g_featn + ((size_t)(b << 12) + j1) * COUT;
        const float* fn2 = g_featn + ((size_t)(b << 12) + j2) * COUT;
        const float* fc1 = sfc + (r1 >> 4) * COUT;
        const float* fc2 = sfc + (r2 >> 4) * COUT;
#pragma unroll
        for (int nt = 0; nt < 8; nt++) {
            const int col = wn * 64 + nt * 8 + (lane & 3) * 2;
            const float2 bq = *(const float2*)(sbp2 + col);
            {
                const float2 fn = *(const float2*)(fn1 + col);
                const float2 fc = *(const float2*)(fc1 + col);
                const float pe0 = acc[mt][nt][0] + bq.x;
                const float pe1 = acc[mt][nt][1] + bq.y;
                float2 v; v.x = fn.x + pe0; v.y = fn.y + pe1;
                *(float2*)(sV + r1 * VPAD + col) = v;
                u32 hi, lo;
                split2(fc.x - fn.x + pe0, fc.y - fn.y + pe1, hi, lo);
                sAhi[r1 * AW + (col >> 1)] = hi;
                sAlo[r1 * AW + (col >> 1)] = lo;
            }
            {
                const float2 fn = *(const float2*)(fn2 + col);
                const float2 fc = *(const float2*)(fc2 + col);
                const float pe0 = acc[mt][nt][2] + bq.x;
                const float pe1 = acc[mt][nt][3] + bq.y;
                float2 v; v.x = fn.x + pe0; v.y = fn.y + pe1;
                *(float2*)(sV + r2 * VPAD + col) = v;
                u32 hi, lo;
                split2(fc.x - fn.x + pe0, fc.y - fn.y + pe1, hi, lo);
                sAhi[r2 * AW + (col >> 1)] = hi;
                sAlo[r2 * AW + (col >> 1)] = lo;
            }
        }
    }
    __syncthreads();

    // --- GEMM2: a1_pre = h @ Wa1 ------------------------------------------
#pragma unroll
    for (int mt = 0; mt < 2; mt++)
#pragma unroll
        for (int nt = 0; nt < 8; nt++) {
            acc[mt][nt][0] = 0.f; acc[mt][nt][1] = 0.f;
            acc[mt][nt][2] = 0.f; acc[mt][nt][3] = 0.f;
        }
    gemm_pass(sb, wm, wn, lane, acc);

    // --- epilogue 2: partial scores (this warp's 64-col half) --------------
#pragma unroll
    for (int mt = 0; mt < 2; mt++) {
        float s1 = 0.0f, s2 = 0.0f;
#pragma unroll
        for (int nt = 0; nt < 8; nt++) {
            const int col = wn * 64 + nt * 8 + (lane & 3) * 2;
            const float2 ba = *(const float2*)(sba1 + col);
            const float2 wv = *(const float2*)(swv + col);
            s1 = fmaf(fmaxf(acc[mt][nt][0] + ba.x, 0.0f), wv.x, s1);
            s1 = fmaf(fmaxf(acc[mt][nt][1] + ba.y, 0.0f), wv.y, s1);
            s2 = fmaf(fmaxf(acc[mt][nt][2] + ba.x, 0.0f), wv.x, s2);
            s2 = fmaf(fmaxf(acc[mt][nt][3] + ba.y, 0.0f), wv.y, s2);
        }
        s1 += __shfl_xor_sync(0xffffffffu, s1, 1);
        s1 += __shfl_xor_sync(0xffffffffu, s1, 2);
        s2 += __shfl_xor_sync(0xffffffffu, s2, 1);
        s2 += __shfl_xor_sync(0xffffffffu, s2, 2);
        if ((lane & 3) == 0) {
            const int r1 = wm * 32 + mt * 16 + (lane >> 2);
            spart[wn * 128 + r1] = s1;
            spart[wn * 128 + r1 + 8] = s2;
        }
    }
    __syncthreads();

    // --- softmax + aggregation --------------------------------------------
    {
        const int p  = tid >> 5;
        const int c4 = (tid & 31) * 4;
        float sc[KNN];
        float m = -1e30f;
#pragma unroll
        for (int k = 0; k < KNN; k++) {
            const int r = p * KNN + k;
            sc[k] = spart[r] + spart[128 + r];
            m = fmaxf(m, sc[k]);
        }
        float s = 0.0f;
#pragma unroll
        for (int k = 0; k < KNN; k++) { sc[k] = expf(sc[k] - m); s += sc[k]; }
        const float inv = 1.0f / s;
        float4 agg = make_float4(0.f, 0.f, 0.f, 0.f);
#pragma unroll
        for (int k = 0; k < KNN; k++) {
            const float wk = sc[k] * inv;
            const float4 v = *(const float4*)(sV + (p * KNN + k) * VPAD + c4);
            agg.x = fmaf(wk, v.x, agg.x);
            agg.y = fmaf(wk, v.y, agg.y);
            agg.z = fmaf(wk, v.z, agg.z);
            agg.w = fmaf(wk, v.w, agg.w);
        }
        const float4 fc = *(const float4*)(sfc + p * COUT + c4);
        float4 o;
        o.x = fc.x + agg.x; o.y = fc.y + agg.y;
        o.z = fc.z + agg.z; o.w = fc.w + agg.w;
        *(float4*)(out + (size_t)(p0g + p) * COUT + c4) = o;
    }
}

// ---------------------------------------------------------------------------
extern "C" void kernel_launch(void* const* d_in, const int* in_sizes, int n_in,
                              void* d_out, int out_size) {
    (void)in_sizes; (void)n_in; (void)out_size;
    const float* x   = (const float*)d_in[0];
    const float* pos = (const float*)d_in[1];
    const float* Wc  = (const float*)d_in[2];
    const float* bc  = (const float*)d_in[3];
    const float* Wn  = (const float*)d_in[4];
    const float* bn  = (const float*)d_in[5];
    const float* Wp1 = (const float*)d_in[6];
    const float* bp1 = (const float*)d_in[7];
    const float* Wp2 = (const float*)d_in[8];
    const float* bp2 = (const float*)d_in[9];
    const float* Wa1 = (const float*)d_in[10];
    const float* ba1 = (const float*)d_in[11];
    const float* Wa2 = (const float*)d_in[12];
    const float* ba2 = (const float*)d_in[13];
    const float* Ws  = (const float*)d_in[14];
    (void)ba2;   // ba2.Ws folds to a softmax-invariant constant -> dropped
    float* out = (float*)d_out;

    cudaFuncSetAttribute(fuse_kernel, cudaFuncAttributeMaxDynamicSharedMemorySize,
                         SMEM_TOTAL);

    prep_kernel<<<65, 256>>>(Wp2, Wa1, Wa2, Ws);
    dim3 kgrid(NPTS / 32, BATCH, 2);
    knn_kernel<<<kgrid, 32 * KSPLIT>>>(pos);
    knn_merge_kernel<<<BATCH * NPTS / 256, 256>>>();
    linear_kernel<<<BATCH * NPTS / 32, 128>>>(x, Wc, bc, Wn, bn);
    fuse_kernel<<<BATCH * NPTS / PTSB, 256, SMEM_TOTAL>>>(pos, Wp1, bp1, bp2, ba1, out);
}

// round 9
// speedup vs baseline: 3.9220x; 1.0705x over previous
#include <cuda_runtime.h>
#include <cuda_bf16.h>
#include <cstdint>

#define BATCH 4
#define NPTS  4096
#define CIN   64
#define COUT  128
#define KNN   16
#define KSPLIT 4
#define PTSB  8            // points per fuse block
#define ROWS  128          // PTSB * KNN
#define APAD  136          // bf16 per padded A/B row
#define AW    68           // u32 words per padded row

typedef unsigned long long u64;
typedef unsigned int u32;

// ---------------- device scratch (no allocations allowed) -------------------
__device__ int   g_idx[BATCH * NPTS * KNN];
__device__ float g_knd[2 * BATCH * NPTS * KNN];
__device__ int   g_kni[2 * BATCH * NPTS * KNN];
__device__ float g_featc[BATCH * NPTS * COUT];
__device__ float g_featn[BATCH * NPTS * COUT];
__device__ float g_fcw[BATCH * NPTS * COUT];   // featc@Wa1 + (bp2@Wa1 + ba1)
__device__ float g_fnw[BATCH * NPTS * COUT];   // featn@Wa1
__device__ float g_u[BATCH * NPTS * COUT];     // sum_k w_k P1_k
__device__ float g_wa2ws[COUT];
__device__ float g_bvec[COUT];
__device__ __align__(16) __nv_bfloat16 gWPA_hi[128 * APAD];  // (Wp2@Wa1)^T image
__device__ __align__(16) __nv_bfloat16 gWPA_lo[128 * APAD];

// ---------------- helpers ----------------------------------------------------
__device__ __forceinline__ void mma_bf16(float* c,
                                         u32 a0, u32 a1, u32 a2, u32 a3,
                                         u32 b0, u32 b1) {
    asm volatile(
        "mma.sync.aligned.m16n8k16.row.col.f32.bf16.bf16.f32 "
        "{%0,%1,%2,%3}, {%4,%5,%6,%7}, {%8,%9}, {%0,%1,%2,%3};"
        : "+f"(c[0]), "+f"(c[1]), "+f"(c[2]), "+f"(c[3])
        : "r"(a0), "r"(a1), "r"(a2), "r"(a3), "r"(b0), "r"(b1));
}
__device__ __forceinline__ void ldsm_x4(u32* r, u32 addr) {
    asm volatile("ldmatrix.sync.aligned.m8n8.x4.shared.b16 {%0,%1,%2,%3}, [%4];"
        : "=r"(r[0]), "=r"(r[1]), "=r"(r[2]), "=r"(r[3]) : "r"(addr));
}
__device__ __forceinline__ u32 smem_u32(const void* p) {
    u32 a;
    asm("{ .reg .u64 t; cvta.to.shared.u64 t, %1; cvt.u32.u64 %0, t; }"
        : "=r"(a) : "l"(p));
    return a;
}
__device__ __forceinline__ void split2(float x, float y, u32& hi, u32& lo) {
    __nv_bfloat16 hx = __float2bfloat16(x);
    __nv_bfloat16 hy = __float2bfloat16(y);
    __nv_bfloat162 hp; hp.x = hx; hp.y = hy;
    __nv_bfloat162 lp;
    lp.x = __float2bfloat16(x - __bfloat162float(hx));
    lp.y = __float2bfloat16(y - __bfloat162float(hy));
    hi = *(u32*)&hp; lo = *(u32*)&lp;
}

// ---------------- fuse SMEM layout (bytes) -----------------------------------
#define OFF_SIDX   0
#define OFF_SPD    512
#define OFF_SFC    2048
#define OFF_SFCW   6144
#define OFF_WV     10240
#define OFF_SPART  10752
#define OFF_SW     11776
#define OFF_P1F    12288
#define OFF_AHI    77824
#define OFF_ALO    112640
#define OFF_BHI    147456
#define OFF_BLO    182272
#define SMEM_TOTAL 217088
#define DLO        34816

// ---------------------------------------------------------------------------
// prep: blocks 0..63 build WPA = Wp2@Wa1 bf16 hi/lo N-major images;
// block 64: wa2ws fold + bvec = bp2@Wa1 + ba1.
// ---------------------------------------------------------------------------
__global__ void prep_kernel(const float* __restrict__ Wp2,
                            const float* __restrict__ Wa1,
                            const float* __restrict__ Wa2,
                            const float* __restrict__ Ws,
                            const float* __restrict__ bp2,
                            const float* __restrict__ ba1) {
    const int blk = blockIdx.x;
    const int tid = threadIdx.x;
    if (blk == 64) {
        if (tid < COUT) {
            float s = 0.0f;
#pragma unroll 8
            for (int j = 0; j < COUT; j++) s = fmaf(Wa2[tid * COUT + j], Ws[j], s);
            g_wa2ws[tid] = s;
        } else {
            const int n = tid - 128;
            float s = ba1[n];
#pragma unroll 8
            for (int j = 0; j < COUT; j++) s = fmaf(bp2[j], Wa1[j * COUT + n], s);
            g_bvec[n] = s;
        }
        return;
    }
    const int idx = blk * 256 + tid;       // 0..16383
    const int n = idx & 127;
    const int k = idx >> 7;
    float v = 0.0f;
#pragma unroll 8
    for (int j = 0; j < COUT; j++) v = fmaf(Wp2[k * COUT + j], Wa1[j * COUT + n], v);
    const int o = n * APAD + k;
    __nv_bfloat16 hi = __float2bfloat16(v);
    gWPA_hi[o] = hi;
    gWPA_lo[o] = __float2bfloat16(v - __bfloat162float(hi));
}

// ---------------------------------------------------------------------------
// knn: blockIdx.z = candidate half; batch-of-8 max filter.
// ---------------------------------------------------------------------------
__global__ void knn_kernel(const float* __restrict__ pos) {
    const int b    = blockIdx.y;
    const int half = blockIdx.z;
    const int lane = threadIdx.x & 31;
    const int w    = threadIdx.x >> 5;
    const int q    = blockIdx.x * 32 + lane;
    const float* posb = pos + (size_t)b * NPTS * 3;

    const float qx = posb[q * 3 + 0];
    const float qy = posb[q * 3 + 1];
    const float qz = posb[q * 3 + 2];

    float bd[KNN];
    int   bi[KNN];
#pragma unroll
    for (int k = 0; k < KNN; k++) { bd[k] = -1e30f; bi[k] = 0; }

    __shared__ float4 tile[KSPLIT][128];
    __shared__ float  sd[KSPLIT][32][KNN];
    __shared__ int    si[KSPLIT][32][KNN];

    const int base = half * 2048 + w * 512;
    for (int t = 0; t < 512; t += 128) {
        __syncwarp();
#pragma unroll
        for (int u = 0; u < 4; u++) {
            const int j = base + t + lane * 4 + u;
            const float x = posb[j * 3 + 0];
            const float y = posb[j * 3 + 1];
            const float z = posb[j * 3 + 2];
            tile[w][lane * 4 + u] = make_float4(x, y, z, -0.5f * (x * x + y * y + z * z));
        }
        __syncwarp();
#pragma unroll 2
        for (int jj = 0; jj < 128; jj += 8) {
            float kk[8];
#pragma unroll
            for (int u = 0; u < 8; u++) {
                const float4 c = tile[w][jj + u];
                kk[u] = fmaf(qx, c.x, fmaf(qy, c.y, fmaf(qz, c.z, c.w)));
            }
            float mx = fmaxf(kk[0], kk[1]);
            mx = fmaxf(mx, fmaxf(kk[2], kk[3]));
            mx = fmaxf(mx, fmaxf(kk[4], kk[5]));
            mx = fmaxf(mx, fmaxf(kk[6], kk[7]));
            if (mx > bd[KNN - 1]) {
#pragma unroll
                for (int u = 0; u < 8; u++) {
                    if (kk[u] > bd[KNN - 1]) {
                        bd[KNN - 1] = kk[u];
                        bi[KNN - 1] = base + t + jj + u;
#pragma unroll
                        for (int s = KNN - 1; s > 0; --s) {
                            if (bd[s] > bd[s - 1]) {
                                const float td = bd[s]; bd[s] = bd[s - 1]; bd[s - 1] = td;
                                const int   ti = bi[s]; bi[s] = bi[s - 1]; bi[s - 1] = ti;
                            }
                        }
                    }
                }
            }
        }
    }
#pragma unroll
    for (int k = 0; k < KNN; k++) { sd[w][lane][k] = bd[k]; si[w][lane][k] = bi[k]; }
    __syncthreads();

    if (threadIdx.x < 32) {
        const int t = threadIdx.x;
        int pp[KSPLIT];
#pragma unroll
        for (int s = 0; s < KSPLIT; s++) pp[s] = 0;
        const size_t qg = (size_t)b * NPTS + blockIdx.x * 32 + t;
        float* outd = g_knd + ((size_t)half * BATCH * NPTS + qg) * KNN;
        int*   outi = g_kni + ((size_t)half * BATCH * NPTS + qg) * KNN;
#pragma unroll
        for (int k = 0; k < KNN; k++) {
            float bestd = -1e31f; int bests = 0, besti = 0x7fffffff;
#pragma unroll
            for (int s = 0; s < KSPLIT; s++) {
                if (pp[s] < KNN) {
                    const float dv = sd[s][t][pp[s]];
                    const int   iv = si[s][t][pp[s]];
                    if (dv > bestd || (dv == bestd && iv < besti)) {
                        bestd = dv; besti = iv; bests = s;
                    }
                }
            }
            outd[k] = bestd; outi[k] = besti;
            pp[bests]++;
        }
    }
}

__global__ void knn_merge_kernel() {
    const size_t q = (size_t)blockIdx.x * blockDim.x + threadIdx.x;
    const float* d0 = g_knd + q * KNN;
    const float* d1 = g_knd + ((size_t)BATCH * NPTS + q) * KNN;
    const int*   i0 = g_kni + q * KNN;
    const int*   i1 = g_kni + ((size_t)BATCH * NPTS + q) * KNN;
    int p0 = 0, p1 = 0;
    int* outp = g_idx + q * KNN;
#pragma unroll
    for (int k = 0; k < KNN; k++) {
        const float a = d0[p0];
        const float c = d1[p1];
        if (a >= c) { outp[k] = i0[p0]; p0++; }
        else        { outp[k] = i1[p1]; p1++; }
    }
}

// ---------------------------------------------------------------------------
// linear: feat_c = x@Wc+bc ; feat_n = x@Wn+bn  (K=64)
// ---------------------------------------------------------------------------
__global__ void __launch_bounds__(128)
linear_kernel(const float* __restrict__ x,
              const float* __restrict__ Wc, const float* __restrict__ bc,
              const float* __restrict__ Wn, const float* __restrict__ bn) {
    const int row0 = blockIdx.x * 32;
    const int tid  = threadIdx.x;
    const int lane = tid & 31;
    const int w    = tid >> 5;
    const int r0   = w * 8;
    const int c4   = lane * 4;

    __shared__ float xs[32 * CIN];
    {
        const float4* src = (const float4*)(x + (size_t)row0 * CIN);
        float4* dst = (float4*)xs;
#pragma unroll
        for (int i = 0; i < 4; i++) dst[tid + i * 128] = src[tid + i * 128];
    }
    __syncthreads();

#pragma unroll
    for (int pass = 0; pass < 2; pass++) {
        const float* W  = pass ? Wn : Wc;
        const float* bb = pass ? bn : bc;
        float* G = pass ? g_featn : g_featc;

        float acc[8][4];
        const float4 b4 = *(const float4*)(bb + c4);
#pragma unroll
        for (int i = 0; i < 8; i++) {
            acc[i][0] = b4.x; acc[i][1] = b4.y; acc[i][2] = b4.z; acc[i][3] = b4.w;
        }
#pragma unroll 4
        for (int k0 = 0; k0 < CIN; k0 += 4) {
            float4 ww[4];
#pragma unroll
            for (int kk = 0; kk < 4; kk++)
                ww[kk] = *(const float4*)(W + (k0 + kk) * COUT + c4);
#pragma unroll
            for (int i = 0; i < 8; i++) {
                const float4 a = *(const float4*)(xs + (r0 + i) * CIN + k0);
                acc[i][0] = fmaf(a.x, ww[0].x, acc[i][0]);
                acc[i][0] = fmaf(a.y, ww[1].x, acc[i][0]);
                acc[i][0] = fmaf(a.z, ww[2].x, acc[i][0]);
                acc[i][0] = fmaf(a.w, ww[3].x, acc[i][0]);
                acc[i][1] = fmaf(a.x, ww[0].y, acc[i][1]);
                acc[i][1] = fmaf(a.y, ww[1].y, acc[i][1]);
                acc[i][1] = fmaf(a.z, ww[2].y, acc[i][1]);
                acc[i][1] = fmaf(a.w, ww[3].y, acc[i][1]);
                acc[i][2] = fmaf(a.x, ww[0].z, acc[i][2]);
                acc[i][2] = fmaf(a.y, ww[1].z, acc[i][2]);
                acc[i][2] = fmaf(a.z, ww[2].z, acc[i][2]);
                acc[i][2] = fmaf(a.w, ww[3].z, acc[i][2]);
                acc[i][3] = fmaf(a.x, ww[0].w, acc[i][3]);
                acc[i][3] = fmaf(a.y, ww[1].w, acc[i][3]);
                acc[i][3] = fmaf(a.z, ww[2].w, acc[i][3]);
                acc[i][3] = fmaf(a.w, ww[3].w, acc[i][3]);
            }
        }
#pragma unroll
        for (int i = 0; i < 8; i++) {
            float4 o; o.x = acc[i][0]; o.y = acc[i][1]; o.z = acc[i][2]; o.w = acc[i][3];
            *(float4*)(G + (size_t)(row0 + r0 + i) * COUT + c4) = o;
        }
    }
}

// ---------------------------------------------------------------------------
// linw: FCW = featc@Wa1 + bvec ; FNW = featn@Wa1  (K=128)
// ---------------------------------------------------------------------------
__global__ void __launch_bounds__(128)
linw_kernel(const float* __restrict__ Wa1) {
    const int row0 = blockIdx.x * 32;
    const int tid  = threadIdx.x;
    const int lane = tid & 31;
    const int w    = tid >> 5;
    const int r0   = w * 8;
    const int c4   = lane * 4;

    __shared__ float xs[32 * COUT];

#pragma unroll
    for (int pass = 0; pass < 2; pass++) {
        const float* X = pass ? g_featn : g_featc;
        float* G = pass ? g_fnw : g_fcw;

        {
            const float4* src = (const float4*)(X + (size_t)row0 * COUT);
            float4* dst = (float4*)xs;
#pragma unroll
            for (int i = 0; i < 8; i++) dst[tid + i * 128] = src[tid + i * 128];
        }
        __syncthreads();

        float acc[8][4];
        if (pass == 0) {
            const float4 b4 = *(const float4*)(g_bvec + c4);
#pragma unroll
            for (int i = 0; i < 8; i++) {
                acc[i][0] = b4.x; acc[i][1] = b4.y; acc[i][2] = b4.z; acc[i][3] = b4.w;
            }
        } else {
#pragma unroll
            for (int i = 0; i < 8; i++) {
                acc[i][0] = 0.f; acc[i][1] = 0.f; acc[i][2] = 0.f; acc[i][3] = 0.f;
            }
        }
#pragma unroll 4
        for (int k0 = 0; k0 < COUT; k0 += 4) {
            float4 ww[4];
#pragma unroll
            for (int kk = 0; kk < 4; kk++)
                ww[kk] = *(const float4*)(Wa1 + (k0 + kk) * COUT + c4);
#pragma unroll
            for (int i = 0; i < 8; i++) {
                const float4 a = *(const float4*)(xs + (r0 + i) * COUT + k0);
                acc[i][0] = fmaf(a.x, ww[0].x, acc[i][0]);
                acc[i][0] = fmaf(a.y, ww[1].x, acc[i][0]);
                acc[i][0] = fmaf(a.z, ww[2].x, acc[i][0]);
                acc[i][0] = fmaf(a.w, ww[3].x, acc[i][0]);
                acc[i][1] = fmaf(a.x, ww[0].y, acc[i][1]);
                acc[i][1] = fmaf(a.y, ww[1].y, acc[i][1]);
                acc[i][1] = fmaf(a.z, ww[2].y, acc[i][1]);
                acc[i][1] = fmaf(a.w, ww[3].y, acc[i][1]);
                acc[i][2] = fmaf(a.x, ww[0].z, acc[i][2]);
                acc[i][2] = fmaf(a.y, ww[1].z, acc[i][2]);
                acc[i][2] = fmaf(a.z, ww[2].z, acc[i][2]);
                acc[i][2] = fmaf(a.w, ww[3].z, acc[i][2]);
                acc[i][3] = fmaf(a.x, ww[0].w, acc[i][3]);
                acc[i][3] = fmaf(a.y, ww[1].w, acc[i][3]);
                acc[i][3] = fmaf(a.z, ww[2].w, acc[i][3]);
                acc[i][3] = fmaf(a.w, ww[3].w, acc[i][3]);
            }
        }
#pragma unroll
        for (int i = 0; i < 8; i++) {
            float4 o; o.x = acc[i][0]; o.y = acc[i][1]; o.z = acc[i][2]; o.w = acc[i][3];
            *(float4*)(G + (size_t)(row0 + r0 + i) * COUT + c4) = o;
        }
        __syncthreads();
    }
}

// ---------------------------------------------------------------------------
// gemm pass (validated in R8): warp (wm, wn) computes rows [32wm,32wm+32) x
// cols [64wn,64wn+64), K=128, ldmatrix.x4 + 3-term bf16 hi/lo mma.sync.
// ---------------------------------------------------------------------------
__device__ __forceinline__ void gemm_pass(u32 sb, int wm, int wn, int lane,
                                          float (&acc)[2][8][4]) {
    const int arow = wm * 32 + ((lane >> 3) & 1) * 8 + (lane & 7);
    const int ak   = (lane >> 4) * 8;
    u32 aB = sb + OFF_AHI + (u32)(arow * (AW * 4) + ak * 2);
    const int nrow = wn * 64 + (lane >> 4) * 8 + (lane & 7);
    const int bk   = ((lane >> 3) & 1) * 8;
    u32 bB = sb + OFF_BHI + (u32)(nrow * (AW * 4) + bk * 2);
#pragma unroll
    for (int kt = 0; kt < 8; kt++) {
        u32 ah0[4], al0[4], ah1[4], al1[4];
        ldsm_x4(ah0, aB);
        ldsm_x4(al0, aB + DLO);
        ldsm_x4(ah1, aB + 16 * (AW * 4));
        ldsm_x4(al1, aB + 16 * (AW * 4) + DLO);
#pragma unroll
        for (int p = 0; p < 4; p++) {
            u32 bh[4], bl[4];
            const u32 ba = bB + p * 16 * (AW * 4);
            ldsm_x4(bh, ba);
            ldsm_x4(bl, ba + DLO);
            mma_bf16(acc[0][2*p],   ah0[0],ah0[1],ah0[2],ah0[3], bh[0],bh[1]);
            mma_bf16(acc[0][2*p],   ah0[0],ah0[1],ah0[2],ah0[3], bl[0],bl[1]);
            mma_bf16(acc[0][2*p],   al0[0],al0[1],al0[2],al0[3], bh[0],bh[1]);
            mma_bf16(acc[0][2*p+1], ah0[0],ah0[1],ah0[2],ah0[3], bh[2],bh[3]);
            mma_bf16(acc[0][2*p+1], ah0[0],ah0[1],ah0[2],ah0[3], bl[2],bl[3]);
            mma_bf16(acc[0][2*p+1], al0[0],al0[1],al0[2],al0[3], bh[2],bh[3]);
            mma_bf16(acc[1][2*p],   ah1[0],ah1[1],ah1[2],ah1[3], bh[0],bh[1]);
            mma_bf16(acc[1][2*p],   ah1[0],ah1[1],ah1[2],ah1[3], bl[0],bl[1]);
            mma_bf16(acc[1][2*p],   al1[0],al1[1],al1[2],al1[3], bh[0],bh[1]);
            mma_bf16(acc[1][2*p+1], ah1[0],ah1[1],ah1[2],ah1[3], bh[2],bh[3]);
            mma_bf16(acc[1][2*p+1], ah1[0],ah1[1],ah1[2],ah1[3], bl[2],bl[3]);
            mma_bf16(acc[1][2*p+1], al1[0],al1[1],al1[2],al1[3], bh[2],bh[3]);
        }
        aB += 32;
        bB += 32;
    }
}

// ---------------------------------------------------------------------------
// fuse: 8 points/block, 256 threads. ONE pair GEMM: acc = P1 @ WPA.
// Scores from acc + FCW - FNW; softmax; aggregate fc + sum(w fn) -> out,
// u = sum(w P1) -> g_u.
// ---------------------------------------------------------------------------
__global__ void __launch_bounds__(256, 1)
fuse_kernel(const float* __restrict__ pos,
            const float* __restrict__ Wp1, const float* __restrict__ bp1,
            float* __restrict__ out) {
    extern __shared__ char smem[];
    const u32 sb   = smem_u32(smem);
    const int tid  = threadIdx.x;
    const int lane = tid & 31;
    const int w    = tid >> 5;
    const int wm   = w & 3;
    const int wn   = w >> 2;
    const int p0g  = blockIdx.x * PTSB;
    const int b    = p0g >> 12;

    int*   sidx  = (int*)(smem + OFF_SIDX);
    float* spd   = (float*)(smem + OFF_SPD);
    float* sfc   = (float*)(smem + OFF_SFC);
    float* sfcw  = (float*)(smem + OFF_SFCW);
    float* swv   = (float*)(smem + OFF_WV);
    float* spart = (float*)(smem + OFF_SPART);
    float* sw    = (float*)(smem + OFF_SW);
    float* sP1   = (float*)(smem + OFF_P1F);
    u32* sAhi = (u32*)(smem + OFF_AHI);
    u32* sAlo = (u32*)(smem + OFF_ALO);
    u32* sBhi = (u32*)(smem + OFF_BHI);
    u32* sBlo = (u32*)(smem + OFF_BLO);

    // --- loads -------------------------------------------------------------
    if (tid < ROWS) sidx[tid] = g_idx[(size_t)p0g * KNN + tid];
    if (tid < COUT) swv[tid] = g_wa2ws[tid];
    {
        const uint4* h = (const uint4*)gWPA_hi;
        const uint4* l = (const uint4*)gWPA_lo;
        uint4* dh = (uint4*)sBhi;
        uint4* dl = (uint4*)sBlo;
#pragma unroll
        for (int i = 0; i < 8; i++) { dh[tid + i * 256] = h[tid + i * 256];
                                      dl[tid + i * 256] = l[tid + i * 256]; }
        if (tid < 128) { dh[tid + 2048] = h[tid + 2048];
                         dl[tid + 2048] = l[tid + 2048]; }
    }
    {
        const float4* s1 = (const float4*)(g_featc + (size_t)p0g * COUT);
        const float4* s2 = (const float4*)(g_fcw + (size_t)p0g * COUT);
        ((float4*)sfc)[tid]  = s1[tid];
        ((float4*)sfcw)[tid] = s2[tid];
    }
    __syncthreads();
    if (tid < ROWS) {
        const int r = tid;
        const int p = r >> 4;
        const int j = sidx[r];
        const float* qp = pos + (size_t)(p0g + p) * 3;
        const float* np = pos + ((size_t)(b << 12) + j) * 3;
        spd[r * 3 + 0] = qp[0] - np[0];
        spd[r * 3 + 1] = qp[1] - np[1];
        spd[r * 3 + 2] = qp[2] - np[2];
    }
    __syncthreads();

    // --- P1 = relu(spd @ Wp1 + bp1): fp32 to sP1, bf16 hi/lo to sA ---------
    {
        const int kp = tid & 63;
        const float2 w0 = *(const float2*)(Wp1 + 0 * COUT + 2 * kp);
        const float2 w1 = *(const float2*)(Wp1 + 1 * COUT + 2 * kp);
        const float2 w2 = *(const float2*)(Wp1 + 2 * COUT + 2 * kp);
        const float2 bb = *(const float2*)(bp1 + 2 * kp);
        for (int r = tid >> 6; r < ROWS; r += 4) {
            const float d0 = spd[r * 3 + 0];
            const float d1 = spd[r * 3 + 1];
            const float d2 = spd[r * 3 + 2];
            float va = fmaxf(fmaf(d0, w0.x, fmaf(d1, w1.x, fmaf(d2, w2.x, bb.x))), 0.0f);
            float vb = fmaxf(fmaf(d0, w0.y, fmaf(d1, w1.y, fmaf(d2, w2.y, bb.y))), 0.0f);
            u32 hi, lo;
            split2(va, vb, hi, lo);
            sAhi[r * AW + kp] = hi;
            sAlo[r * AW + kp] = lo;
            float2 pf; pf.x = va; pf.y = vb;
            *(float2*)(sP1 + r * COUT + 2 * kp) = pf;
        }
    }
    __syncthreads();

    // --- GEMM: acc = P1 @ WPA ---------------------------------------------
    float acc[2][8][4];
#pragma unroll
    for (int mt = 0; mt < 2; mt++)
#pragma unroll
        for (int nt = 0; nt < 8; nt++) {
            acc[mt][nt][0] = 0.f; acc[mt][nt][1] = 0.f;
            acc[mt][nt][2] = 0.f; acc[mt][nt][3] = 0.f;
        }
    gemm_pass(sb, wm, wn, lane, acc);

    // --- score epilogue: a1pre = acc + FCW[i] - FNW[j]; partials -----------
#pragma unroll
    for (int mt = 0; mt < 2; mt++) {
        const int r1 = wm * 32 + mt * 16 + (lane >> 2);
        const int r2 = r1 + 8;
        const int j1 = sidx[r1], j2 = sidx[r2];
        const float* fnw1 = g_fnw + ((size_t)(b << 12) + j1) * COUT;
        const float* fnw2 = g_fnw + ((size_t)(b << 12) + j2) * COUT;
        const float* fcw1 = sfcw + (r1 >> 4) * COUT;
        const float* fcw2 = sfcw + (r2 >> 4) * COUT;
        float s1 = 0.0f, s2 = 0.0f;
#pragma unroll
        for (int nt = 0; nt < 8; nt++) {
            const int col = wn * 64 + nt * 8 + (lane & 3) * 2;
            const float2 wv = *(const float2*)(swv + col);
            {
                const float2 fw = *(const float2*)(fcw1 + col);
                const float2 fn = *(const float2*)(fnw1 + col);
                s1 = fmaf(fmaxf(acc[mt][nt][0] + fw.x - fn.x, 0.0f), wv.x, s1);
                s1 = fmaf(fmaxf(acc[mt][nt][1] + fw.y - fn.y, 0.0f), wv.y, s1);
            }
            {
                const float2 fw = *(const float2*)(fcw2 + col);
                const float2 fn = *(const float2*)(fnw2 + col);
                s2 = fmaf(fmaxf(acc[mt][nt][2] + fw.x - fn.x, 0.0f), wv.x, s2);
                s2 = fmaf(fmaxf(acc[mt][nt][3] + fw.y - fn.y, 0.0f), wv.y, s2);
            }
        }
        s1 += __shfl_xor_sync(0xffffffffu, s1, 1);
        s1 += __shfl_xor_sync(0xffffffffu, s1, 2);
        s2 += __shfl_xor_sync(0xffffffffu, s2, 1);
        s2 += __shfl_xor_sync(0xffffffffu, s2, 2);
        if ((lane & 3) == 0) {
            spart[wn * 128 + r1] = s1;
            spart[wn * 128 + r2] = s2;
        }
    }
    __syncthreads();

    // --- softmax weights ---------------------------------------------------
    {
        const int p = tid >> 5;
        float sc[KNN];
        float m = -1e30f;
#pragma unroll
        for (int k = 0; k < KNN; k++) {
            const int r = p * KNN + k;
            sc[k] = spart[r] + spart[128 + r];
            m = fmaxf(m, sc[k]);
        }
        float s = 0.0f;
#pragma unroll
        for (int k = 0; k < KNN; k++) { sc[k] = expf(sc[k] - m); s += sc[k]; }
        const float inv = 1.0f / s;
        if (lane < KNN) sw[p * KNN + lane] = sc[lane] * inv;
    }
    __syncthreads();

    // --- aggregation: out = fc + sum(w fn); u = sum(w P1) ------------------
    {
        const int p  = tid >> 5;
        const int c4 = lane * 4;
        float4 g4 = *(const float4*)(sfc + p * COUT + c4);
        float4 u4 = make_float4(0.f, 0.f, 0.f, 0.f);
#pragma unroll
        for (int k = 0; k < KNN; k++) {
            const float wk = sw[p * KNN + k];
            const int r = p * KNN + k;
            const int j = sidx[r];
            const float4 fn = *(const float4*)(g_featn + ((size_t)(b << 12) + j) * COUT + c4);
            g4.x = fmaf(wk, fn.x, g4.x);
            g4.y = fmaf(wk, fn.y, g4.y);
            g4.z = fmaf(wk, fn.z, g4.z);
            g4.w = fmaf(wk, fn.w, g4.w);
            const float4 pv = *(const float4*)(sP1 + r * COUT + c4);
            u4.x = fmaf(wk, pv.x, u4.x);
            u4.y = fmaf(wk, pv.y, u4.y);
            u4.z = fmaf(wk, pv.z, u4.z);
            u4.w = fmaf(wk, pv.w, u4.w);
        }
        *(float4*)(out + (size_t)(p0g + p) * COUT + c4) = g4;
        *(float4*)(g_u + (size_t)(p0g + p) * COUT + c4) = u4;
    }
}

// ---------------------------------------------------------------------------
// final: out += u @ Wp2 + bp2   (K=128 dense)
// ---------------------------------------------------------------------------
__global__ void __launch_bounds__(128)
final_kernel(const float* __restrict__ Wp2, const float* __restrict__ bp2,
             float* __restrict__ out) {
    const int row0 = blockIdx.x * 32;
    const int tid  = threadIdx.x;
    const int lane = tid & 31;
    const int w    = tid >> 5;
    const int r0   = w * 8;
    const int c4   = lane * 4;

    __shared__ float us[32 * COUT];
    {
        const float4* src = (const float4*)(g_u + (size_t)row0 * COUT);
        float4* dst = (float4*)us;
#pragma unroll
        for (int i = 0; i < 8; i++) dst[tid + i * 128] = src[tid + i * 128];
    }
    __syncthreads();

    float acc[8][4];
    const float4 b4 = *(const float4*)(bp2 + c4);
#pragma unroll
    for (int i = 0; i < 8; i++) {
        acc[i][0] = b4.x; acc[i][1] = b4.y; acc[i][2] = b4.z; acc[i][3] = b4.w;
    }
#pragma unroll 4
    for (int k0 = 0; k0 < COUT; k0 += 4) {
        float4 ww[4];
#pragma unroll
        for (int kk = 0; kk < 4; kk++)
            ww[kk] = *(const float4*)(Wp2 + (k0 + kk) * COUT + c4);
#pragma unroll
        for (int i = 0; i < 8; i++) {
            const float4 a = *(const float4*)(us + (r0 + i) * COUT + k0);
            acc[i][0] = fmaf(a.x, ww[0].x, acc[i][0]);
            acc[i][0] = fmaf(a.y, ww[1].x, acc[i][0]);
            acc[i][0] = fmaf(a.z, ww[2].x, acc[i][0]);
            acc[i][0] = fmaf(a.w, ww[3].x, acc[i][0]);
            acc[i][1] = fmaf(a.x, ww[0].y, acc[i][1]);
            acc[i][1] = fmaf(a.y, ww[1].y, acc[i][1]);
            acc[i][1] = fmaf(a.z, ww[2].y, acc[i][1]);
            acc[i][1] = fmaf(a.w, ww[3].y, acc[i][1]);
            acc[i][2] = fmaf(a.x, ww[0].z, acc[i][2]);
            acc[i][2] = fmaf(a.y, ww[1].z, acc[i][2]);
            acc[i][2] = fmaf(a.z, ww[2].z, acc[i][2]);
            acc[i][2] = fmaf(a.w, ww[3].z, acc[i][2]);
            acc[i][3] = fmaf(a.x, ww[0].w, acc[i][3]);
            acc[i][3] = fmaf(a.y, ww[1].w, acc[i][3]);
            acc[i][3] = fmaf(a.z, ww[2].w, acc[i][3]);
            acc[i][3] = fmaf(a.w, ww[3].w, acc[i][3]);
        }
    }
#pragma unroll
    for (int i = 0; i < 8; i++) {
        float* op = out + (size_t)(row0 + r0 + i) * COUT + c4;
        float4 prev = *(const float4*)op;
        float4 o;
        o.x = prev.x + acc[i][0]; o.y = prev.y + acc[i][1];
        o.z = prev.z + acc[i][2]; o.w = prev.w + acc[i][3];
        *(float4*)op = o;
    }
}

// ---------------------------------------------------------------------------
extern "C" void kernel_launch(void* const* d_in, const int* in_sizes, int n_in,
                              void* d_out, int out_size) {
    (void)in_sizes; (void)n_in; (void)out_size;
    const float* x   = (const float*)d_in[0];
    const float* pos = (const float*)d_in[1];
    const float* Wc  = (const float*)d_in[2];
    const float* bc  = (const float*)d_in[3];
    const float* Wn  = (const float*)d_in[4];
    const float* bn  = (const float*)d_in[5];
    const float* Wp1 = (const float*)d_in[6];
    const float* bp1 = (const float*)d_in[7];
    const float* Wp2 = (const float*)d_in[8];
    const float* bp2 = (const float*)d_in[9];
    const float* Wa1 = (const float*)d_in[10];
    const float* ba1 = (const float*)d_in[11];
    const float* Wa2 = (const float*)d_in[12];
    const float* ba2 = (const float*)d_in[13];
    const float* Ws  = (const float*)d_in[14];
    (void)ba2;   // ba2.Ws folds to a softmax-invariant constant -> dropped
    float* out = (float*)d_out;

    cudaFuncSetAttribute(fuse_kernel, cudaFuncAttributeMaxDynamicSharedMemorySize,
                         SMEM_TOTAL);

    prep_kernel<<<65, 256>>>(Wp2, Wa1, Wa2, Ws, bp2, ba1);
    dim3 kgrid(NPTS / 32, BATCH, 2);
    knn_kernel<<<kgrid, 32 * KSPLIT>>>(pos);
    knn_merge_kernel<<<BATCH * NPTS / 256, 256>>>();
    linear_kernel<<<BATCH * NPTS / 32, 128>>>(x, Wc, bc, Wn, bn);
    linw_kernel<<<BATCH * NPTS / 32, 128>>>(Wa1);
    fuse_kernel<<<BATCH * NPTS / PTSB, 256, SMEM_TOTAL>>>(pos, Wp1, bp1, out);
    final_kernel<<<BATCH * NPTS / 32, 128>>>(Wp2, bp2, out);
}